// round 2
// baseline (speedup 1.0000x reference)
#include <cuda_runtime.h>

#define BATCH 4
#define NVOX  32768
#define NROWS (BATCH*NVOX)
#define C     128
#define NCLS  10
#define TOPK  500
#define PAD   132

// ---------------- device scratch (no allocations allowed) ----------------
__device__ __align__(16) float g_Wf[6*C*C];        // BN-folded W1
__device__ float g_bf[6*C];                        // BN-folded bias
__device__ float g_hm[BATCH*NCLS*NVOX];            // sigmoid scores, [b][cls][v]
__device__ float g_cand_score[BATCH*NCLS*TOPK];
__device__ int   g_cand_vox[BATCH*NCLS*TOPK];
__device__ float g_sel_score[BATCH*TOPK];
__device__ int   g_sel_cls[BATCH*TOPK];
__device__ int   g_sel_vox[BATCH*TOPK];

// ---------------- kernel 0: fold BN into W1/b1 ----------------
__global__ void fold_kernel(const float* __restrict__ W1, const float* __restrict__ b1,
                            const float* __restrict__ gam, const float* __restrict__ bet,
                            const float* __restrict__ mu,  const float* __restrict__ var) {
    int i = blockIdx.x * blockDim.x + threadIdx.x;
    if (i >= 6*C*C) return;
    int c  = i % C;
    int hk = i / C;          // = h*C + k
    int h  = hk / C;
    int k  = hk - h*C;
    int hc = h*C + c;
    float inv = gam[hc] / sqrtf(var[hc] + 1e-5f);
    g_Wf[i] = W1[i] * inv;
    if (k == 0) g_bf[hc] = (b1[hc] - mu[hc]) * inv + bet[hc];
}

// ---------------- kernel 1: dense hm head (fp32 GEMM, fused epilogue) ----------------
// Per block: 128 rows. H = relu(X @ Wf0 + bf0); hm = sigmoid(H @ W2 + b2).
// Writes g_hm transposed [b][cls][v] for coalesced topk reads.
__global__ void __launch_bounds__(256, 1)
hm_kernel(const float* __restrict__ feats,
          const float* __restrict__ W2, const float* __restrict__ b2) {
    extern __shared__ float sm1[];
    float* Xst = sm1;                 // [128 k][PAD rows]  (X transposed)
    float* Wsh = sm1 + C*PAD;         // [128 k][PAD cols], later reused as H[row][PAD]
    float* W2s = Wsh + C*PAD;         // [128*10]
    float* bfs = W2s + C*NCLS;        // [128]

    int tid  = threadIdx.x;
    int row0 = blockIdx.x * 128;

    // load X tile (transposed into smem)
    for (int t = tid; t < C*32; t += 256) {
        int r  = t >> 5;
        int c4 = (t & 31) << 2;
        float4 f = *reinterpret_cast<const float4*>(feats + (long)(row0 + r)*C + c4);
        Xst[(c4+0)*PAD + r] = f.x;
        Xst[(c4+1)*PAD + r] = f.y;
        Xst[(c4+2)*PAD + r] = f.z;
        Xst[(c4+3)*PAD + r] = f.w;
    }
    // load folded W (head 0), bias, W2
    for (int t = tid; t < C*32; t += 256) {
        int kk = t >> 5;
        int c4 = (t & 31) << 2;
        *reinterpret_cast<float4*>(Wsh + kk*PAD + c4) =
            *reinterpret_cast<const float4*>(g_Wf + kk*C + c4);
    }
    if (tid < C) bfs[tid] = g_bf[tid];
    for (int t = tid; t < C*NCLS; t += 256) W2s[t] = W2[t];
    __syncthreads();

    int ty = tid >> 4, tx = tid & 15;
    int rowBase = ty * 8, colBase = tx * 8;

    float acc[8][8];
    #pragma unroll
    for (int i = 0; i < 8; i++)
        #pragma unroll
        for (int j = 0; j < 8; j++) acc[i][j] = 0.f;

    #pragma unroll 8
    for (int kk = 0; kk < C; kk++) {
        float a[8], bb[8];
        *reinterpret_cast<float4*>(a)    = *reinterpret_cast<const float4*>(Xst + kk*PAD + rowBase);
        *reinterpret_cast<float4*>(a+4)  = *reinterpret_cast<const float4*>(Xst + kk*PAD + rowBase + 4);
        *reinterpret_cast<float4*>(bb)   = *reinterpret_cast<const float4*>(Wsh + kk*PAD + colBase);
        *reinterpret_cast<float4*>(bb+4) = *reinterpret_cast<const float4*>(Wsh + kk*PAD + colBase + 4);
        #pragma unroll
        for (int i = 0; i < 8; i++)
            #pragma unroll
            for (int j = 0; j < 8; j++) acc[i][j] += a[i] * bb[j];
    }
    __syncthreads();   // done reading Wsh as weights

    // bias + relu, stash H into Wsh[row][col]
    #pragma unroll
    for (int i = 0; i < 8; i++)
        #pragma unroll
        for (int j = 0; j < 8; j++) {
            float v = acc[i][j] + bfs[colBase + j];
            Wsh[(rowBase + i)*PAD + (colBase + j)] = fmaxf(v, 0.f);
        }
    __syncthreads();

    // second linear (oc=10) + sigmoid, one row per thread
    if (tid < 128) {
        float o[NCLS];
        #pragma unroll
        for (int j = 0; j < NCLS; j++) o[j] = __ldg(b2 + j);
        for (int kk = 0; kk < C; kk++) {
            float hv = Wsh[tid*PAD + kk];
            #pragma unroll
            for (int j = 0; j < NCLS; j++) o[j] += hv * W2s[kk*NCLS + j];
        }
        int row = row0 + tid;
        int b   = row >> 15;         // / NVOX
        int v   = row & (NVOX - 1);
        #pragma unroll
        for (int j = 0; j < NCLS; j++) {
            float s = 1.f / (1.f + expf(-o[j]));
            g_hm[((long)(b*NCLS + j))*NVOX + v] = s;
        }
    }
}

// ---------------- kernel 2: per-(batch,class) exact top-500 (radix select) ----------------
__device__ __forceinline__ unsigned key_of(float f) {
    unsigned u = __float_as_uint(f);
    return (u & 0x80000000u) ? ~u : (u | 0x80000000u);
}
__device__ __forceinline__ float float_of(unsigned k) {
    unsigned u = (k & 0x80000000u) ? (k & 0x7FFFFFFFu) : ~k;
    return __uint_as_float(u);
}

__global__ void topk_class_kernel() {
    extern __shared__ unsigned skey[];       // 32768 keys = 128 KB
    __shared__ int hist[256];
    __shared__ unsigned sh_prefix, sh_mask;
    __shared__ int sh_rem;
    __shared__ int cgt, ceq;

    int bc  = blockIdx.x;                    // b*10 + cls
    int tid = threadIdx.x, nt = blockDim.x;
    const float* src = g_hm + (long)bc * NVOX;

    for (int v = tid; v < NVOX; v += nt) skey[v] = key_of(src[v]);
    if (tid == 0) { sh_prefix = 0; sh_mask = 0; sh_rem = TOPK; }
    __syncthreads();

    for (int shift = 24; shift >= 0; shift -= 8) {
        for (int i = tid; i < 256; i += nt) hist[i] = 0;
        __syncthreads();
        unsigned mask = sh_mask, pref = sh_prefix;
        for (int v = tid; v < NVOX; v += nt) {
            unsigned k = skey[v];
            if ((k & mask) == pref) atomicAdd(&hist[(k >> shift) & 0xFF], 1);
        }
        __syncthreads();
        if (tid == 0) {
            int rem = sh_rem, cum = 0, b = 0;
            for (b = 255; b > 0; b--) { cum += hist[b]; if (cum >= rem) break; }
            if (cum < rem) cum += hist[0];           // b == 0 fallthrough
            sh_rem    = rem - (cum - hist[b]);
            sh_prefix = pref | ((unsigned)b << shift);
            sh_mask   = mask | (0xFFu << shift);
        }
        __syncthreads();
    }
    unsigned T = sh_prefix;
    int nEq = sh_rem;
    int nGt = TOPK - nEq;
    if (tid == 0) { cgt = 0; ceq = 0; }
    __syncthreads();

    float* outS = g_cand_score + bc * TOPK;
    int*   outV = g_cand_vox   + bc * TOPK;
    for (int v = tid; v < NVOX; v += nt) {
        unsigned k = skey[v];
        int slot = -1;
        if (k > T)       slot = atomicAdd(&cgt, 1);
        else if (k == T) { int q = atomicAdd(&ceq, 1); if (q < nEq) slot = nGt + q; }
        if (slot >= 0) { outS[slot] = src[v]; outV[slot] = v; }
    }
}

// ---------------- kernel 3: per-batch global top-500 (bitonic sort 8192) ----------------
__global__ void global_topk_kernel() {
    extern __shared__ unsigned long long sk3[];   // 8192 * 8B = 64 KB
    int b = blockIdx.x, tid = threadIdx.x, nt = blockDim.x;
    const float* cs = g_cand_score + b * NCLS * TOPK;

    for (int i = tid; i < 8192; i += nt) {
        unsigned long long it = 0ull;
        if (i < NCLS*TOPK)
            it = (((unsigned long long)key_of(cs[i])) << 32) | (unsigned)i;
        sk3[i] = it;
    }
    __syncthreads();
    for (int k = 2; k <= 8192; k <<= 1) {
        for (int j = k >> 1; j > 0; j >>= 1) {
            for (int i = tid; i < 8192; i += nt) {
                int ixj = i ^ j;
                if (ixj > i) {
                    bool up = ((i & k) == 0);   // ascending overall
                    unsigned long long a = sk3[i], c = sk3[ixj];
                    if (up ? (a > c) : (a < c)) { sk3[i] = c; sk3[ixj] = a; }
                }
            }
            __syncthreads();
        }
    }
    if (tid < TOPK) {
        unsigned long long it = sk3[8191 - tid];   // rank tid (descending)
        int idx = (int)(it & 0xFFFFFFFFu);
        g_sel_score[b*TOPK + tid] = float_of((unsigned)(it >> 32));
        g_sel_cls  [b*TOPK + tid] = idx / TOPK;
        g_sel_vox  [b*TOPK + tid] = g_cand_vox[b*NCLS*TOPK + idx];
    }
}

// ---------------- kernel 4: 5 small heads only for selected rows + decode ----------------
__global__ void __launch_bounds__(128)
gather_decode_kernel(const float* __restrict__ feats, const int* __restrict__ voxel_xy,
                     const float* __restrict__ W2c, const float* __restrict__ b2c,
                     const float* __restrict__ W2z, const float* __restrict__ b2z,
                     const float* __restrict__ W2d, const float* __restrict__ b2d,
                     const float* __restrict__ W2r, const float* __restrict__ b2r,
                     const float* __restrict__ W2v, const float* __restrict__ b2v,
                     float* __restrict__ out) {
    int e = blockIdx.x;                 // 0..1999
    int b = e / TOPK, k = e % TOPK;
    int tid = threadIdx.x;
    __shared__ float xr[C], hs[C], res[10];

    float score = g_sel_score[e];
    int   cls   = g_sel_cls[e];
    int   vox   = g_sel_vox[e];
    int   row   = b * NVOX + vox;

    xr[tid] = feats[(long)row*C + tid];
    __syncthreads();

    const float* W2p[5] = {W2c, W2z, W2d, W2r, W2v};
    const float* b2p[5] = {b2c, b2z, b2d, b2r, b2v};
    const int    ocp[5] = {2, 1, 3, 2, 2};
    const int    sbp[5] = {0, 2, 3, 6, 8};

    #pragma unroll
    for (int hh = 0; hh < 5; hh++) {
        int h = hh + 1;
        const float* w = g_Wf + h*C*C + tid;
        float s0 = 0.f, s1 = 0.f, s2 = 0.f, s3 = 0.f;
        #pragma unroll 8
        for (int kk = 0; kk < C; kk += 4) {
            s0 += xr[kk+0] * w[(kk+0)*C];
            s1 += xr[kk+1] * w[(kk+1)*C];
            s2 += xr[kk+2] * w[(kk+2)*C];
            s3 += xr[kk+3] * w[(kk+3)*C];
        }
        float s = ((s0 + s1) + (s2 + s3)) + g_bf[h*C + tid];
        hs[tid] = fmaxf(s, 0.f);
        __syncthreads();
        if (tid < ocp[hh]) {
            int oc = ocp[hh];
            const float* w2 = W2p[hh];
            float acc = __ldg(b2p[hh] + tid);
            for (int kk = 0; kk < C; kk++) acc += hs[kk] * w2[kk*oc + tid];
            res[sbp[hh] + tid] = (hh == 2) ? expf(acc) : acc;
        }
        __syncthreads();
    }

    if (tid == 0) {
        float vx = (float)voxel_xy[row*2 + 0];
        float vy = (float)voxel_xy[row*2 + 1];
        float xs = (vx + res[0]) * 0.6f - 54.0f;   // STRIDE*VOX = 8*0.075
        float ys = (vy + res[1]) * 0.6f - 54.0f;
        float cz = res[2];
        float ang = atan2f(res[7], res[6]);
        bool m = (xs >= -61.2f) && (xs <= 61.2f) &&
                 (ys >= -61.2f) && (ys <= 61.2f) &&
                 (cz >= -10.f)  && (cz <= 10.f)  && (score > 0.1f);
        float mf = m ? 1.f : 0.f;
        float* ob = out + (long)(b*TOPK + k) * 10;
        ob[0] = xs * mf;  ob[1] = ys * mf;  ob[2] = cz * mf;
        ob[3] = res[3] * mf; ob[4] = res[4] * mf; ob[5] = res[5] * mf;
        ob[6] = ang * mf; ob[7] = res[8] * mf; ob[8] = res[9] * mf;
        ob[9] = score * mf;
        int base = b*TOPK + k;
        out[BATCH*TOPK*10            + base] = m ? (float)(cls + 1) : 0.f;  // labels
        out[BATCH*TOPK*10 + BATCH*TOPK   + base] = (float)(vox + b*NVOX);   // voxel_ids
        out[BATCH*TOPK*10 + 2*BATCH*TOPK + base] = mf;                      // mask
    }
}

// ---------------- host launcher ----------------
extern "C" void kernel_launch(void* const* d_in, const int* in_sizes, int n_in,
                              void* d_out, int out_size) {
    const float* feats    = (const float*)d_in[0];
    const int*   voxel_xy = (const int*)d_in[1];
    const float* W1  = (const float*)d_in[2];
    const float* b1  = (const float*)d_in[3];
    const float* gam = (const float*)d_in[4];
    const float* bet = (const float*)d_in[5];
    const float* mu  = (const float*)d_in[6];
    const float* var = (const float*)d_in[7];
    const float* W2_hm = (const float*)d_in[8];
    const float* b2_hm = (const float*)d_in[9];
    const float* W2_c  = (const float*)d_in[10];
    const float* b2_c  = (const float*)d_in[11];
    const float* W2_z  = (const float*)d_in[12];
    const float* b2_z  = (const float*)d_in[13];
    const float* W2_d  = (const float*)d_in[14];
    const float* b2_d  = (const float*)d_in[15];
    const float* W2_r  = (const float*)d_in[16];
    const float* b2_r  = (const float*)d_in[17];
    const float* W2_v  = (const float*)d_in[18];
    const float* b2_v  = (const float*)d_in[19];
    float* out = (float*)d_out;

    const int smem1 = (C*PAD*2 + C*NCLS + C) * (int)sizeof(float);   // ~141.8 KB
    const int smem2 = NVOX * (int)sizeof(unsigned);                   // 128 KB
    const int smem3 = 8192 * (int)sizeof(unsigned long long);         // 64 KB
    cudaFuncSetAttribute(hm_kernel,          cudaFuncAttributeMaxDynamicSharedMemorySize, smem1);
    cudaFuncSetAttribute(topk_class_kernel,  cudaFuncAttributeMaxDynamicSharedMemorySize, smem2);
    cudaFuncSetAttribute(global_topk_kernel, cudaFuncAttributeMaxDynamicSharedMemorySize, smem3);

    fold_kernel<<<(6*C*C + 255) / 256, 256>>>(W1, b1, gam, bet, mu, var);
    hm_kernel<<<NROWS / 128, 256, smem1>>>(feats, W2_hm, b2_hm);
    topk_class_kernel<<<BATCH * NCLS, 1024, smem2>>>();
    global_topk_kernel<<<BATCH, 1024, smem3>>>();
    gather_decode_kernel<<<BATCH * TOPK, 128>>>(feats, voxel_xy,
                                                W2_c, b2_c, W2_z, b2_z, W2_d, b2_d,
                                                W2_r, b2_r, W2_v, b2_v, out);
}

// round 3
// speedup vs baseline: 1.1513x; 1.1513x over previous
#include <cuda_runtime.h>

#define BATCH 4
#define NVOX  32768
#define NROWS (BATCH*NVOX)
#define C     128
#define NCLS  10
#define TOPK  500
#define PAD   132
#define NCHUNK 4
#define CHUNK  (NVOX/NCHUNK)          // 8192
#define CAND_PER_B (NCLS*NCHUNK*TOPK) // 20000
#define GD_BATCH 8

// ---------------- device scratch ----------------
__device__ __align__(16) float g_Wf[6*C*C];
__device__ float g_bf[6*C];
__device__ float g_hm[BATCH*NCLS*NVOX];
__device__ float g_cand_score[BATCH*CAND_PER_B];
__device__ int   g_cand_vox[BATCH*CAND_PER_B];
__device__ float g_sel_score[BATCH*TOPK];
__device__ int   g_sel_cls[BATCH*TOPK];
__device__ int   g_sel_vox[BATCH*TOPK];

// ---------------- kernel 0: fold BN into W1/b1 ----------------
__global__ void fold_kernel(const float* __restrict__ W1, const float* __restrict__ b1,
                            const float* __restrict__ gam, const float* __restrict__ bet,
                            const float* __restrict__ mu,  const float* __restrict__ var) {
    int i = blockIdx.x * blockDim.x + threadIdx.x;
    if (i >= 6*C*C) return;
    int c  = i % C;
    int hk = i / C;
    int h  = hk / C;
    int k  = hk - h*C;
    int hc = h*C + c;
    float inv = gam[hc] / sqrtf(var[hc] + 1e-5f);
    g_Wf[i] = W1[i] * inv;
    if (k == 0) g_bf[hc] = (b1[hc] - mu[hc]) * inv + bet[hc];
}

// ---------------- kernel 1: dense hm head (fp32 GEMM, fused epilogue) ----------------
__global__ void __launch_bounds__(256, 1)
hm_kernel(const float* __restrict__ feats,
          const float* __restrict__ W2, const float* __restrict__ b2) {
    extern __shared__ float sm1[];
    float* Xst = sm1;                 // [128 k][PAD rows]
    float* Wsh = sm1 + C*PAD;         // [128 k][PAD cols] -> reused as H[row][PAD]
    float* W2s = Wsh + C*PAD;         // [128*10]
    float* bfs = W2s + C*NCLS;        // [128]

    int tid  = threadIdx.x;
    int row0 = blockIdx.x * 128;

    for (int t = tid; t < C*32; t += 256) {
        int r  = t >> 5;
        int c4 = (t & 31) << 2;
        float4 f = *reinterpret_cast<const float4*>(feats + (long)(row0 + r)*C + c4);
        Xst[(c4+0)*PAD + r] = f.x;
        Xst[(c4+1)*PAD + r] = f.y;
        Xst[(c4+2)*PAD + r] = f.z;
        Xst[(c4+3)*PAD + r] = f.w;
    }
    for (int t = tid; t < C*32; t += 256) {
        int kk = t >> 5;
        int c4 = (t & 31) << 2;
        *reinterpret_cast<float4*>(Wsh + kk*PAD + c4) =
            *reinterpret_cast<const float4*>(g_Wf + kk*C + c4);
    }
    if (tid < C) bfs[tid] = g_bf[tid];
    for (int t = tid; t < C*NCLS; t += 256) W2s[t] = W2[t];
    __syncthreads();

    int ty = tid >> 4, tx = tid & 15;
    int rowBase = ty * 8, colBase = tx * 8;

    float acc[8][8];
    #pragma unroll
    for (int i = 0; i < 8; i++)
        #pragma unroll
        for (int j = 0; j < 8; j++) acc[i][j] = 0.f;

    #pragma unroll 8
    for (int kk = 0; kk < C; kk++) {
        float a[8], bb[8];
        *reinterpret_cast<float4*>(a)    = *reinterpret_cast<const float4*>(Xst + kk*PAD + rowBase);
        *reinterpret_cast<float4*>(a+4)  = *reinterpret_cast<const float4*>(Xst + kk*PAD + rowBase + 4);
        *reinterpret_cast<float4*>(bb)   = *reinterpret_cast<const float4*>(Wsh + kk*PAD + colBase);
        *reinterpret_cast<float4*>(bb+4) = *reinterpret_cast<const float4*>(Wsh + kk*PAD + colBase + 4);
        #pragma unroll
        for (int i = 0; i < 8; i++)
            #pragma unroll
            for (int j = 0; j < 8; j++) acc[i][j] += a[i] * bb[j];
    }
    __syncthreads();

    #pragma unroll
    for (int i = 0; i < 8; i++)
        #pragma unroll
        for (int j = 0; j < 8; j++) {
            float v = acc[i][j] + bfs[colBase + j];
            Wsh[(rowBase + i)*PAD + (colBase + j)] = fmaxf(v, 0.f);
        }
    __syncthreads();

    // second linear (oc=10) + sigmoid: 2 threads per row, 5 classes each
    {
        int row = tid >> 1;
        int j0  = (tid & 1) * 5;
        float o[5];
        #pragma unroll
        for (int j = 0; j < 5; j++) o[j] = __ldg(b2 + j0 + j);
        for (int kk = 0; kk < C; kk++) {
            float hv = Wsh[row*PAD + kk];
            #pragma unroll
            for (int j = 0; j < 5; j++) o[j] += hv * W2s[kk*NCLS + j0 + j];
        }
        int rrow = row0 + row;
        int b    = rrow >> 15;
        int v    = rrow & (NVOX - 1);
        #pragma unroll
        for (int j = 0; j < 5; j++) {
            float s = 1.f / (1.f + expf(-o[j]));
            g_hm[((long)(b*NCLS + j0 + j))*NVOX + v] = s;
        }
    }
}

// ---------------- radix helpers ----------------
__device__ __forceinline__ unsigned key_of(float f) {
    unsigned u = __float_as_uint(f);
    return (u & 0x80000000u) ? ~u : (u | 0x80000000u);
}
__device__ __forceinline__ float float_of(unsigned k) {
    unsigned u = (k & 0x80000000u) ? (k & 0x7FFFFFFFu) : ~k;
    return __uint_as_float(u);
}

// ---------------- kernel 2: per-(b,cls,chunk) local top-500 of 8192 ----------------
// Chunk top-500 is a superset of the class-top entries in that chunk, so the
// union over chunks is a superset of the per-class top-500, which is a superset
// of the global top-500. Exactness of the final answer is preserved.
__global__ void __launch_bounds__(512)
topk_chunk_kernel() {
    __shared__ unsigned skey[CHUNK];          // 32 KB
    __shared__ int hist[256];
    __shared__ unsigned sh_prefix, sh_mask;
    __shared__ int sh_rem, cgt, ceq;

    int blk = blockIdx.x;                     // (bc*NCHUNK + chunk)
    int bc  = blk >> 2, chunk = blk & 3;
    int tid = threadIdx.x, nt = blockDim.x;
    const float* src = g_hm + (long)bc * NVOX + chunk * CHUNK;

    for (int v = tid; v < CHUNK; v += nt) skey[v] = key_of(src[v]);
    if (tid == 0) { sh_prefix = 0; sh_mask = 0; sh_rem = TOPK; }
    __syncthreads();

    for (int shift = 24; shift >= 0; shift -= 8) {
        for (int i = tid; i < 256; i += nt) hist[i] = 0;
        __syncthreads();
        unsigned mask = sh_mask, pref = sh_prefix;
        for (int v = tid; v < CHUNK; v += nt) {
            unsigned k = skey[v];
            if ((k & mask) == pref) atomicAdd(&hist[(k >> shift) & 0xFF], 1);
        }
        __syncthreads();
        if (tid == 0) {
            int rem = sh_rem, cum = 0, b = 255;
            for (b = 255; b > 0; b--) { cum += hist[b]; if (cum >= rem) break; }
            if (cum < rem) cum += hist[0];
            sh_rem    = rem - (cum - hist[b]);
            sh_prefix = pref | ((unsigned)b << shift);
            sh_mask   = mask | (0xFFu << shift);
        }
        __syncthreads();
    }
    unsigned T = sh_prefix;
    int nEq = sh_rem;
    int nGt = TOPK - nEq;
    if (tid == 0) { cgt = 0; ceq = 0; }
    __syncthreads();

    float* outS = g_cand_score + blk * TOPK;
    int*   outV = g_cand_vox   + blk * TOPK;
    int voff = chunk * CHUNK;
    for (int v = tid; v < CHUNK; v += nt) {
        unsigned k = skey[v];
        int slot = -1;
        if (k > T)       slot = atomicAdd(&cgt, 1);
        else if (k == T) { int q = atomicAdd(&ceq, 1); if (q < nEq) slot = nGt + q; }
        if (slot >= 0) { outS[slot] = src[v]; outV[slot] = voff + v; }
    }
}

// ---------------- kernel 3: per-batch top-500 of 20000 candidates + sort 512 ----------------
__global__ void global_topk_kernel() {
    extern __shared__ unsigned sm3[];               // 20000 keys + sort buffer
    unsigned* skey = sm3;                            // [20000]
    unsigned long long* sortb = (unsigned long long*)(sm3 + CAND_PER_B);  // [512]
    __shared__ int hist[256];
    __shared__ unsigned sh_prefix, sh_mask;
    __shared__ int sh_rem, cgt, ceq;

    int b = blockIdx.x, tid = threadIdx.x, nt = blockDim.x;
    const float* cs = g_cand_score + (long)b * CAND_PER_B;

    for (int i = tid; i < CAND_PER_B; i += nt) skey[i] = key_of(cs[i]);
    if (tid < 512) sortb[tid] = 0ull;
    if (tid == 0) { sh_prefix = 0; sh_mask = 0; sh_rem = TOPK; }
    __syncthreads();

    for (int shift = 24; shift >= 0; shift -= 8) {
        for (int i = tid; i < 256; i += nt) hist[i] = 0;
        __syncthreads();
        unsigned mask = sh_mask, pref = sh_prefix;
        for (int i = tid; i < CAND_PER_B; i += nt) {
            unsigned k = skey[i];
            if ((k & mask) == pref) atomicAdd(&hist[(k >> shift) & 0xFF], 1);
        }
        __syncthreads();
        if (tid == 0) {
            int rem = sh_rem, cum = 0, bb = 255;
            for (bb = 255; bb > 0; bb--) { cum += hist[bb]; if (cum >= rem) break; }
            if (cum < rem) cum += hist[0];
            sh_rem    = rem - (cum - hist[bb]);
            sh_prefix = pref | ((unsigned)bb << shift);
            sh_mask   = mask | (0xFFu << shift);
        }
        __syncthreads();
    }
    unsigned T = sh_prefix;
    int nEq = sh_rem;
    int nGt = TOPK - nEq;
    if (tid == 0) { cgt = 0; ceq = 0; }
    __syncthreads();

    for (int i = tid; i < CAND_PER_B; i += nt) {
        unsigned k = skey[i];
        int slot = -1;
        if (k > T)       slot = atomicAdd(&cgt, 1);
        else if (k == T) { int q = atomicAdd(&ceq, 1); if (q < nEq) slot = nGt + q; }
        if (slot >= 0)
            sortb[slot] = (((unsigned long long)k) << 32) | (unsigned)i;
    }
    __syncthreads();

    // bitonic sort 512 (ascending); zero padding sinks to the bottom
    for (int k = 2; k <= 512; k <<= 1) {
        for (int j = k >> 1; j > 0; j >>= 1) {
            if (tid < 512) {
                int i = tid, ixj = i ^ j;
                if (ixj > i) {
                    bool up = ((i & k) == 0);
                    unsigned long long a = sortb[i], c = sortb[ixj];
                    if (up ? (a > c) : (a < c)) { sortb[i] = c; sortb[ixj] = a; }
                }
            }
            __syncthreads();
        }
    }
    if (tid < TOPK) {
        unsigned long long it = sortb[511 - tid];       // rank tid (descending)
        int idx = (int)(it & 0xFFFFFFFFu);
        g_sel_score[b*TOPK + tid] = float_of((unsigned)(it >> 32));
        g_sel_cls  [b*TOPK + tid] = idx / (NCHUNK*TOPK);   // 2000 candidates per class
        g_sel_vox  [b*TOPK + tid] = g_cand_vox[(long)b*CAND_PER_B + idx];
    }
}

// ---------------- kernel 4: 5 small heads for selected rows + decode (8 cands/block) ----------------
__global__ void __launch_bounds__(128)
gather_decode_kernel(const float* __restrict__ feats, const int* __restrict__ voxel_xy,
                     const float* __restrict__ W2c, const float* __restrict__ b2c,
                     const float* __restrict__ W2z, const float* __restrict__ b2z,
                     const float* __restrict__ W2d, const float* __restrict__ b2d,
                     const float* __restrict__ W2r, const float* __restrict__ b2r,
                     const float* __restrict__ W2v, const float* __restrict__ b2v,
                     float* __restrict__ out) {
    int e0  = blockIdx.x * GD_BATCH;
    int tid = threadIdx.x;
    __shared__ float xr[GD_BATCH][C];
    __shared__ float hs[GD_BATCH][C];
    __shared__ float res[GD_BATCH][10];
    __shared__ int   svox[GD_BATCH];

    if (tid < GD_BATCH) svox[tid] = g_sel_vox[e0 + tid];
    __syncthreads();

    #pragma unroll
    for (int c = 0; c < GD_BATCH; c++) {
        int e = e0 + c;
        int row = (e / TOPK) * NVOX + svox[c];
        xr[c][tid] = feats[(long)row*C + tid];
    }
    __syncthreads();

    const float* W2p[5] = {W2c, W2z, W2d, W2r, W2v};
    const float* b2p[5] = {b2c, b2z, b2d, b2r, b2v};
    const int    ocp[5] = {2, 1, 3, 2, 2};
    const int    sbp[5] = {0, 2, 3, 6, 8};

    #pragma unroll
    for (int hh = 0; hh < 5; hh++) {
        int h = hh + 1;
        const float* w = g_Wf + h*C*C + tid;
        float acc[GD_BATCH];
        #pragma unroll
        for (int c = 0; c < GD_BATCH; c++) acc[c] = 0.f;
        #pragma unroll 4
        for (int kk = 0; kk < C; kk++) {
            float wv = w[kk*C];
            #pragma unroll
            for (int c = 0; c < GD_BATCH; c++) acc[c] += xr[c][kk] * wv;
        }
        float bb = g_bf[h*C + tid];
        #pragma unroll
        for (int c = 0; c < GD_BATCH; c++) hs[c][tid] = fmaxf(acc[c] + bb, 0.f);
        __syncthreads();

        int cand = tid >> 4, col = tid & 15;
        int oc = ocp[hh];
        if (col < oc) {
            const float* w2 = W2p[hh];
            float a2 = __ldg(b2p[hh] + col);
            for (int kk = 0; kk < C; kk++) a2 += hs[cand][kk] * __ldg(w2 + kk*oc + col);
            res[cand][sbp[hh] + col] = (hh == 2) ? expf(a2) : a2;
        }
        __syncthreads();
    }

    if (tid < GD_BATCH) {
        int e = e0 + tid;
        int b = e / TOPK, k = e % TOPK;
        float score = g_sel_score[e];
        int   cls   = g_sel_cls[e];
        int   vox   = svox[tid];
        int   row   = b * NVOX + vox;
        float vx = (float)voxel_xy[row*2 + 0];
        float vy = (float)voxel_xy[row*2 + 1];
        float xs = (vx + res[tid][0]) * 0.6f - 54.0f;
        float ys = (vy + res[tid][1]) * 0.6f - 54.0f;
        float cz = res[tid][2];
        float ang = atan2f(res[tid][7], res[tid][6]);
        bool m = (xs >= -61.2f) && (xs <= 61.2f) &&
                 (ys >= -61.2f) && (ys <= 61.2f) &&
                 (cz >= -10.f)  && (cz <= 10.f)  && (score > 0.1f);
        float mf = m ? 1.f : 0.f;
        float* ob = out + (long)(b*TOPK + k) * 10;
        ob[0] = xs * mf;  ob[1] = ys * mf;  ob[2] = cz * mf;
        ob[3] = res[tid][3] * mf; ob[4] = res[tid][4] * mf; ob[5] = res[tid][5] * mf;
        ob[6] = ang * mf; ob[7] = res[tid][8] * mf; ob[8] = res[tid][9] * mf;
        ob[9] = score * mf;
        int base = b*TOPK + k;
        out[BATCH*TOPK*10                 + base] = m ? (float)(cls + 1) : 0.f;
        out[BATCH*TOPK*10 + BATCH*TOPK   + base] = (float)(vox + b*NVOX);
        out[BATCH*TOPK*10 + 2*BATCH*TOPK + base] = mf;
    }
}

// ---------------- host launcher ----------------
extern "C" void kernel_launch(void* const* d_in, const int* in_sizes, int n_in,
                              void* d_out, int out_size) {
    const float* feats    = (const float*)d_in[0];
    const int*   voxel_xy = (const int*)d_in[1];
    const float* W1  = (const float*)d_in[2];
    const float* b1  = (const float*)d_in[3];
    const float* gam = (const float*)d_in[4];
    const float* bet = (const float*)d_in[5];
    const float* mu  = (const float*)d_in[6];
    const float* var = (const float*)d_in[7];
    const float* W2_hm = (const float*)d_in[8];
    const float* b2_hm = (const float*)d_in[9];
    const float* W2_c  = (const float*)d_in[10];
    const float* b2_c  = (const float*)d_in[11];
    const float* W2_z  = (const float*)d_in[12];
    const float* b2_z  = (const float*)d_in[13];
    const float* W2_d  = (const float*)d_in[14];
    const float* b2_d  = (const float*)d_in[15];
    const float* W2_r  = (const float*)d_in[16];
    const float* b2_r  = (const float*)d_in[17];
    const float* W2_v  = (const float*)d_in[18];
    const float* b2_v  = (const float*)d_in[19];
    float* out = (float*)d_out;

    const int smem1 = (C*PAD*2 + C*NCLS + C) * (int)sizeof(float);      // ~142 KB
    const int smem3 = CAND_PER_B * (int)sizeof(unsigned) + 512 * 8;     // ~84 KB
    cudaFuncSetAttribute(hm_kernel,          cudaFuncAttributeMaxDynamicSharedMemorySize, smem1);
    cudaFuncSetAttribute(global_topk_kernel, cudaFuncAttributeMaxDynamicSharedMemorySize, smem3);

    fold_kernel<<<(6*C*C + 255) / 256, 256>>>(W1, b1, gam, bet, mu, var);
    hm_kernel<<<NROWS / 128, 256, smem1>>>(feats, W2_hm, b2_hm);
    topk_chunk_kernel<<<BATCH * NCLS * NCHUNK, 512>>>();
    global_topk_kernel<<<BATCH, 1024, smem3>>>();
    gather_decode_kernel<<<BATCH * TOPK / GD_BATCH, 128>>>(feats, voxel_xy,
                                                W2_c, b2_c, W2_z, b2_z, W2_d, b2_d,
                                                W2_r, b2_r, W2_v, b2_v, out);
}

// round 4
// speedup vs baseline: 1.2077x; 1.0490x over previous
#include <cuda_runtime.h>

#define BATCH 4
#define NVOX  32768
#define NROWS (BATCH*NVOX)
#define C     128
#define NCLS  10
#define TOPK  500
#define PAD   132
#define NCHUNK 4
#define CHUNK  (NVOX/NCHUNK)          // 8192
#define CAND_PER_B (NCLS*NCHUNK*TOPK) // 20000
#define GD_BATCH 8

// ---------------- device scratch ----------------
__device__ __align__(16) float g_Wf[6*C*C];
__device__ float g_bf[6*C];
__device__ float g_hm[BATCH*NCLS*NVOX];           // raw logits (pre-sigmoid)
__device__ float g_cand_score[BATCH*CAND_PER_B];  // logits
__device__ int   g_cand_vox[BATCH*CAND_PER_B];
__device__ float g_sel_score[BATCH*TOPK];         // logits
__device__ int   g_sel_cls[BATCH*TOPK];
__device__ int   g_sel_vox[BATCH*TOPK];

// ---------------- kernel 0: fold BN into W1/b1 ----------------
__global__ void fold_kernel(const float* __restrict__ W1, const float* __restrict__ b1,
                            const float* __restrict__ gam, const float* __restrict__ bet,
                            const float* __restrict__ mu,  const float* __restrict__ var) {
    int i = blockIdx.x * blockDim.x + threadIdx.x;
    if (i >= 6*C*C) return;
    int c  = i % C;
    int hk = i / C;
    int h  = hk / C;
    int k  = hk - h*C;
    int hc = h*C + c;
    float inv = gam[hc] / sqrtf(var[hc] + 1e-5f);
    g_Wf[i] = W1[i] * inv;
    if (k == 0) g_bf[hc] = (b1[hc] - mu[hc]) * inv + bet[hc];
}

// ---------------- kernel 1: dense hm head (fp32 GEMM, fused epilogue) ----------------
__global__ void __launch_bounds__(256, 1)
hm_kernel(const float* __restrict__ feats,
          const float* __restrict__ W2, const float* __restrict__ b2) {
    extern __shared__ float sm1[];
    float* Xst = sm1;                 // [128 k][PAD rows]
    float* Wsh = sm1 + C*PAD;         // [128 k][PAD cols] -> reused as H[row][PAD]
    float* W2s = Wsh + C*PAD;         // [128*10]
    float* bfs = W2s + C*NCLS;        // [128]

    int tid  = threadIdx.x;
    int row0 = blockIdx.x * 128;

    for (int t = tid; t < C*32; t += 256) {
        int r  = t >> 5;
        int c4 = (t & 31) << 2;
        float4 f = *reinterpret_cast<const float4*>(feats + (long)(row0 + r)*C + c4);
        Xst[(c4+0)*PAD + r] = f.x;
        Xst[(c4+1)*PAD + r] = f.y;
        Xst[(c4+2)*PAD + r] = f.z;
        Xst[(c4+3)*PAD + r] = f.w;
    }
    for (int t = tid; t < C*32; t += 256) {
        int kk = t >> 5;
        int c4 = (t & 31) << 2;
        *reinterpret_cast<float4*>(Wsh + kk*PAD + c4) =
            *reinterpret_cast<const float4*>(g_Wf + kk*C + c4);
    }
    if (tid < C) bfs[tid] = g_bf[tid];
    for (int t = tid; t < C*NCLS; t += 256) W2s[t] = W2[t];
    __syncthreads();

    int ty = tid >> 4, tx = tid & 15;
    int rowBase = ty * 8, colBase = tx * 8;

    float acc[8][8];
    #pragma unroll
    for (int i = 0; i < 8; i++)
        #pragma unroll
        for (int j = 0; j < 8; j++) acc[i][j] = 0.f;

    #pragma unroll 8
    for (int kk = 0; kk < C; kk++) {
        float a[8], bb[8];
        *reinterpret_cast<float4*>(a)    = *reinterpret_cast<const float4*>(Xst + kk*PAD + rowBase);
        *reinterpret_cast<float4*>(a+4)  = *reinterpret_cast<const float4*>(Xst + kk*PAD + rowBase + 4);
        *reinterpret_cast<float4*>(bb)   = *reinterpret_cast<const float4*>(Wsh + kk*PAD + colBase);
        *reinterpret_cast<float4*>(bb+4) = *reinterpret_cast<const float4*>(Wsh + kk*PAD + colBase + 4);
        #pragma unroll
        for (int i = 0; i < 8; i++)
            #pragma unroll
            for (int j = 0; j < 8; j++) acc[i][j] += a[i] * bb[j];
    }
    __syncthreads();

    #pragma unroll
    for (int i = 0; i < 8; i++)
        #pragma unroll
        for (int j = 0; j < 8; j++) {
            float v = acc[i][j] + bfs[colBase + j];
            Wsh[(rowBase + i)*PAD + (colBase + j)] = fmaxf(v, 0.f);
        }
    __syncthreads();

    // second linear (oc=10): 2 threads per row, 5 classes each. Store RAW logits.
    {
        int row = tid >> 1;
        int j0  = (tid & 1) * 5;
        float o[5];
        #pragma unroll
        for (int j = 0; j < 5; j++) o[j] = __ldg(b2 + j0 + j);
        for (int kk = 0; kk < C; kk++) {
            float hv = Wsh[row*PAD + kk];
            #pragma unroll
            for (int j = 0; j < 5; j++) o[j] += hv * W2s[kk*NCLS + j0 + j];
        }
        int rrow = row0 + row;
        int b    = rrow >> 15;
        int v    = rrow & (NVOX - 1);
        #pragma unroll
        for (int j = 0; j < 5; j++)
            g_hm[((long)(b*NCLS + j0 + j))*NVOX + v] = o[j];
    }
}

// ---------------- radix helpers ----------------
__device__ __forceinline__ unsigned key_of(float f) {
    unsigned u = __float_as_uint(f);
    return (u & 0x80000000u) ? ~u : (u | 0x80000000u);
}
__device__ __forceinline__ float float_of(unsigned k) {
    unsigned u = (k & 0x80000000u) ? (k & 0x7FFFFFFFu) : ~k;
    return __uint_as_float(u);
}

// warp-aggregated histogram add: one atomic per distinct bin per warp
__device__ __forceinline__ void hist_add(int* hist, unsigned bin, bool act) {
    unsigned lm = __activemask();
    unsigned amask = __ballot_sync(lm, act);
    if (act) {
        unsigned peers = __match_any_sync(amask, bin);
        int leader = __ffs(peers) - 1;
        if ((int)(threadIdx.x & 31) == leader)
            atomicAdd(&hist[bin], __popc(peers));
    }
}

// parallel suffix-scan over hist[256]; returns chosen bucket + updates rem.
// Requires blockDim >= 256. ssum/hist in shared.
__device__ __forceinline__ void pick_bucket(int* hist, int* ssum,
                                            unsigned* sh_prefix, unsigned* sh_mask,
                                            int* sh_rem, int shift) {
    int tid = threadIdx.x;
    if (tid < 256) ssum[tid] = hist[tid];
    __syncthreads();
    #pragma unroll
    for (int off = 1; off < 256; off <<= 1) {
        int v = 0;
        if (tid < 256 && tid + off < 256) v = ssum[tid + off];
        __syncthreads();
        if (tid < 256) ssum[tid] += v;
        __syncthreads();
    }
    // ssum[b] = count of keys with byte >= b (within current prefix)
    int rem = *sh_rem;
    if (tid < 256) {
        int here = ssum[tid];
        int above = (tid == 255) ? 0 : ssum[tid + 1];
        if (here >= rem && above < rem) {        // unique b
            *sh_rem    = rem - above;
            *sh_prefix = *sh_prefix | ((unsigned)tid << shift);
        }
    }
    __syncthreads();
    if (tid == 0) *sh_mask = *sh_mask | (0xFFu << shift);
    __syncthreads();
}

// ---------------- kernel 2: per-(b,cls,chunk) local top-500 of 8192 ----------------
__global__ void __launch_bounds__(512)
topk_chunk_kernel() {
    __shared__ unsigned skey[CHUNK];          // 32 KB
    __shared__ int hist[256];
    __shared__ int ssum[256];
    __shared__ unsigned sh_prefix, sh_mask;
    __shared__ int sh_rem, cgt, ceq;

    int blk = blockIdx.x;                     // (bc*NCHUNK + chunk)
    int bc  = blk >> 2, chunk = blk & 3;
    int tid = threadIdx.x, nt = blockDim.x;
    const float* src = g_hm + (long)bc * NVOX + chunk * CHUNK;

    for (int v = tid; v < CHUNK; v += nt) skey[v] = key_of(src[v]);
    if (tid == 0) { sh_prefix = 0; sh_mask = 0; sh_rem = TOPK; }
    __syncthreads();

    for (int shift = 24; shift >= 0; shift -= 8) {
        for (int i = tid; i < 256; i += nt) hist[i] = 0;
        __syncthreads();
        unsigned mask = sh_mask, pref = sh_prefix;
        for (int v = tid; v < CHUNK; v += nt) {
            unsigned k = skey[v];
            hist_add(hist, (k >> shift) & 0xFF, (k & mask) == pref);
        }
        __syncthreads();
        pick_bucket(hist, ssum, &sh_prefix, &sh_mask, &sh_rem, shift);
    }
    unsigned T = sh_prefix;
    int nEq = sh_rem;
    int nGt = TOPK - nEq;
    if (tid == 0) { cgt = 0; ceq = 0; }
    __syncthreads();

    float* outS = g_cand_score + blk * TOPK;
    int*   outV = g_cand_vox   + blk * TOPK;
    int voff = chunk * CHUNK;
    for (int v = tid; v < CHUNK; v += nt) {
        unsigned k = skey[v];
        int slot = -1;
        if (k > T)       slot = atomicAdd(&cgt, 1);
        else if (k == T) { int q = atomicAdd(&ceq, 1); if (q < nEq) slot = nGt + q; }
        if (slot >= 0) { outS[slot] = src[v]; outV[slot] = voff + v; }
    }
}

// ---------------- kernel 3: per-batch top-500 of 20000 candidates + sort 512 ----------------
__global__ void global_topk_kernel() {
    extern __shared__ unsigned sm3[];               // 20000 keys + sort buffer
    unsigned* skey = sm3;                            // [20000]
    unsigned long long* sortb = (unsigned long long*)(sm3 + CAND_PER_B);  // [512]
    __shared__ int hist[256];
    __shared__ int ssum[256];
    __shared__ unsigned sh_prefix, sh_mask;
    __shared__ int sh_rem, cgt, ceq;

    int b = blockIdx.x, tid = threadIdx.x, nt = blockDim.x;
    const float* cs = g_cand_score + (long)b * CAND_PER_B;

    for (int i = tid; i < CAND_PER_B; i += nt) skey[i] = key_of(cs[i]);
    if (tid < 512) sortb[tid] = 0ull;
    if (tid == 0) { sh_prefix = 0; sh_mask = 0; sh_rem = TOPK; }
    __syncthreads();

    for (int shift = 24; shift >= 0; shift -= 8) {
        for (int i = tid; i < 256; i += nt) hist[i] = 0;
        __syncthreads();
        unsigned mask = sh_mask, pref = sh_prefix;
        for (int i = tid; i < CAND_PER_B; i += nt) {
            unsigned k = skey[i];
            hist_add(hist, (k >> shift) & 0xFF, (k & mask) == pref);
        }
        __syncthreads();
        pick_bucket(hist, ssum, &sh_prefix, &sh_mask, &sh_rem, shift);
    }
    unsigned T = sh_prefix;
    int nEq = sh_rem;
    int nGt = TOPK - nEq;
    if (tid == 0) { cgt = 0; ceq = 0; }
    __syncthreads();

    for (int i = tid; i < CAND_PER_B; i += nt) {
        unsigned k = skey[i];
        int slot = -1;
        if (k > T)       slot = atomicAdd(&cgt, 1);
        else if (k == T) { int q = atomicAdd(&ceq, 1); if (q < nEq) slot = nGt + q; }
        if (slot >= 0)
            sortb[slot] = (((unsigned long long)k) << 32) | (unsigned)i;
    }
    __syncthreads();

    for (int k = 2; k <= 512; k <<= 1) {
        for (int j = k >> 1; j > 0; j >>= 1) {
            if (tid < 512) {
                int i = tid, ixj = i ^ j;
                if (ixj > i) {
                    bool up = ((i & k) == 0);
                    unsigned long long a = sortb[i], c = sortb[ixj];
                    if (up ? (a > c) : (a < c)) { sortb[i] = c; sortb[ixj] = a; }
                }
            }
            __syncthreads();
        }
    }
    if (tid < TOPK) {
        unsigned long long it = sortb[511 - tid];       // rank tid (descending)
        int idx = (int)(it & 0xFFFFFFFFu);
        g_sel_score[b*TOPK + tid] = float_of((unsigned)(it >> 32));
        g_sel_cls  [b*TOPK + tid] = idx / (NCHUNK*TOPK);
        g_sel_vox  [b*TOPK + tid] = g_cand_vox[(long)b*CAND_PER_B + idx];
    }
}

// ---------------- kernel 4: 5 small heads for selected rows + decode ----------------
__global__ void __launch_bounds__(128)
gather_decode_kernel(const float* __restrict__ feats, const int* __restrict__ voxel_xy,
                     const float* __restrict__ W2c, const float* __restrict__ b2c,
                     const float* __restrict__ W2z, const float* __restrict__ b2z,
                     const float* __restrict__ W2d, const float* __restrict__ b2d,
                     const float* __restrict__ W2r, const float* __restrict__ b2r,
                     const float* __restrict__ W2v, const float* __restrict__ b2v,
                     float* __restrict__ out) {
    int e0  = blockIdx.x * GD_BATCH;
    int tid = threadIdx.x;
    __shared__ float xr[GD_BATCH][C];
    __shared__ float hs[GD_BATCH][C];
    __shared__ float res[GD_BATCH][10];
    __shared__ int   svox[GD_BATCH];

    if (tid < GD_BATCH) svox[tid] = g_sel_vox[e0 + tid];
    __syncthreads();

    #pragma unroll
    for (int c = 0; c < GD_BATCH; c++) {
        int e = e0 + c;
        int row = (e / TOPK) * NVOX + svox[c];
        xr[c][tid] = feats[(long)row*C + tid];
    }
    __syncthreads();

    const float* W2p[5] = {W2c, W2z, W2d, W2r, W2v};
    const float* b2p[5] = {b2c, b2z, b2d, b2r, b2v};
    const int    ocp[5] = {2, 1, 3, 2, 2};
    const int    sbp[5] = {0, 2, 3, 6, 8};

    #pragma unroll
    for (int hh = 0; hh < 5; hh++) {
        int h = hh + 1;
        const float* w = g_Wf + h*C*C + tid;
        float acc[GD_BATCH];
        #pragma unroll
        for (int c = 0; c < GD_BATCH; c++) acc[c] = 0.f;
        #pragma unroll 4
        for (int kk = 0; kk < C; kk++) {
            float wv = w[kk*C];
            #pragma unroll
            for (int c = 0; c < GD_BATCH; c++) acc[c] += xr[c][kk] * wv;
        }
        float bb = g_bf[h*C + tid];
        #pragma unroll
        for (int c = 0; c < GD_BATCH; c++) hs[c][tid] = fmaxf(acc[c] + bb, 0.f);
        __syncthreads();

        int cand = tid >> 4, col = tid & 15;
        int oc = ocp[hh];
        if (col < oc) {
            const float* w2 = W2p[hh];
            float a2 = __ldg(b2p[hh] + col);
            for (int kk = 0; kk < C; kk++) a2 += hs[cand][kk] * __ldg(w2 + kk*oc + col);
            res[cand][sbp[hh] + col] = (hh == 2) ? expf(a2) : a2;
        }
        __syncthreads();
    }

    if (tid < GD_BATCH) {
        int e = e0 + tid;
        int b = e / TOPK, k = e % TOPK;
        float score = 1.f / (1.f + expf(-g_sel_score[e]));   // sigmoid only here
        int   cls   = g_sel_cls[e];
        int   vox   = svox[tid];
        int   row   = b * NVOX + vox;
        float vx = (float)voxel_xy[row*2 + 0];
        float vy = (float)voxel_xy[row*2 + 1];
        float xs = (vx + res[tid][0]) * 0.6f - 54.0f;
        float ys = (vy + res[tid][1]) * 0.6f - 54.0f;
        float cz = res[tid][2];
        float ang = atan2f(res[tid][7], res[tid][6]);
        bool m = (xs >= -61.2f) && (xs <= 61.2f) &&
                 (ys >= -61.2f) && (ys <= 61.2f) &&
                 (cz >= -10.f)  && (cz <= 10.f)  && (score > 0.1f);
        float mf = m ? 1.f : 0.f;
        float* ob = out + (long)(b*TOPK + k) * 10;
        ob[0] = xs * mf;  ob[1] = ys * mf;  ob[2] = cz * mf;
        ob[3] = res[tid][3] * mf; ob[4] = res[tid][4] * mf; ob[5] = res[tid][5] * mf;
        ob[6] = ang * mf; ob[7] = res[tid][8] * mf; ob[8] = res[tid][9] * mf;
        ob[9] = score * mf;
        int base = b*TOPK + k;
        out[BATCH*TOPK*10                 + base] = m ? (float)(cls + 1) : 0.f;
        out[BATCH*TOPK*10 + BATCH*TOPK   + base] = (float)(vox + b*NVOX);
        out[BATCH*TOPK*10 + 2*BATCH*TOPK + base] = mf;
    }
}

// ---------------- host launcher ----------------
extern "C" void kernel_launch(void* const* d_in, const int* in_sizes, int n_in,
                              void* d_out, int out_size) {
    const float* feats    = (const float*)d_in[0];
    const int*   voxel_xy = (const int*)d_in[1];
    const float* W1  = (const float*)d_in[2];
    const float* b1  = (const float*)d_in[3];
    const float* gam = (const float*)d_in[4];
    const float* bet = (const float*)d_in[5];
    const float* mu  = (const float*)d_in[6];
    const float* var = (const float*)d_in[7];
    const float* W2_hm = (const float*)d_in[8];
    const float* b2_hm = (const float*)d_in[9];
    const float* W2_c  = (const float*)d_in[10];
    const float* b2_c  = (const float*)d_in[11];
    const float* W2_z  = (const float*)d_in[12];
    const float* b2_z  = (const float*)d_in[13];
    const float* W2_d  = (const float*)d_in[14];
    const float* b2_d  = (const float*)d_in[15];
    const float* W2_r  = (const float*)d_in[16];
    const float* b2_r  = (const float*)d_in[17];
    const float* W2_v  = (const float*)d_in[18];
    const float* b2_v  = (const float*)d_in[19];
    float* out = (float*)d_out;

    const int smem1 = (C*PAD*2 + C*NCLS + C) * (int)sizeof(float);      // ~142 KB
    const int smem3 = CAND_PER_B * (int)sizeof(unsigned) + 512 * 8;     // ~84 KB
    cudaFuncSetAttribute(hm_kernel,          cudaFuncAttributeMaxDynamicSharedMemorySize, smem1);
    cudaFuncSetAttribute(global_topk_kernel, cudaFuncAttributeMaxDynamicSharedMemorySize, smem3);

    fold_kernel<<<(6*C*C + 255) / 256, 256>>>(W1, b1, gam, bet, mu, var);
    hm_kernel<<<NROWS / 128, 256, smem1>>>(feats, W2_hm, b2_hm);
    topk_chunk_kernel<<<BATCH * NCLS * NCHUNK, 512>>>();
    global_topk_kernel<<<BATCH, 1024, smem3>>>();
    gather_decode_kernel<<<BATCH * TOPK / GD_BATCH, 128>>>(feats, voxel_xy,
                                                W2_c, b2_c, W2_z, b2_z, W2_d, b2_d,
                                                W2_r, b2_r, W2_v, b2_v, out);
}

// round 6
// speedup vs baseline: 1.5074x; 1.2482x over previous
#include <cuda_runtime.h>
#include <cstdint>

#define BATCH 4
#define NVOX  32768
#define NROWS (BATCH*NVOX)
#define C     128
#define NCLS  10
#define TOPK  500
#define NCHUNK 4
#define CHUNK  (NVOX/NCHUNK)          // 8192
#define CAND_PER_B (NCLS*NCHUNK*TOPK) // 20000
#define GD_BATCH 8

// hm mma.sync config
#define HM_BLOCKS 256
#define TILES_PER_BLOCK (NROWS/128/HM_BLOCKS)   // 4
#define XPAD 132
#define WPAD 136
// dynamic smem layout in floats
#define SM_XS  0                    // [128][132]
#define SM_WH  (128*XPAD)           // 16896: [128][136] tf32-hi
#define SM_WL  (SM_WH + 128*WPAD)   // 34304: tf32-lo
#define SM_W2  (SM_WL + 128*WPAD)   // 51712: [128][10]
#define SM_BF  (SM_W2 + C*NCLS)     // 52992: [128]
#define SM_FLOATS (SM_BF + 128)     // 53120 -> 212480 bytes

// ---------------- device scratch ----------------
__device__ __align__(16) float g_Wf[6*C*C];
__device__ float g_bf[6*C];
__device__ __align__(16) float g_Whi[128*WPAD];   // [k][136] tf32 hi of folded W0
__device__ __align__(16) float g_Wlo[128*WPAD];   // [k][136] tf32 lo
__device__ float g_hm[BATCH*NCLS*NVOX];           // raw logits
__device__ float g_cand_score[BATCH*CAND_PER_B];
__device__ int   g_cand_vox[BATCH*CAND_PER_B];
__device__ float g_sel_score[BATCH*TOPK];
__device__ int   g_sel_cls[BATCH*TOPK];
__device__ int   g_sel_vox[BATCH*TOPK];

__device__ __forceinline__ uint32_t f2tf32(float x) {
    uint32_t u;
    asm("cvt.rna.tf32.f32 %0, %1;" : "=r"(u) : "f"(x));
    return u;
}
__device__ __forceinline__ void mma_tf32(float* d, const uint32_t* a, const uint32_t* b) {
    asm volatile("mma.sync.aligned.m16n8k8.row.col.f32.tf32.tf32.f32 "
        "{%0,%1,%2,%3}, {%4,%5,%6,%7}, {%8,%9}, {%0,%1,%2,%3};"
        : "+f"(d[0]), "+f"(d[1]), "+f"(d[2]), "+f"(d[3])
        : "r"(a[0]), "r"(a[1]), "r"(a[2]), "r"(a[3]), "r"(b[0]), "r"(b[1]));
}

// ---------------- kernel 0: fold BN; emit tf32 hi/lo of W0^ (as [k][c]) ----------------
__global__ void fold_kernel(const float* __restrict__ W1, const float* __restrict__ b1,
                            const float* __restrict__ gam, const float* __restrict__ bet,
                            const float* __restrict__ mu,  const float* __restrict__ var) {
    int i = blockIdx.x * blockDim.x + threadIdx.x;
    if (i >= 6*C*C) return;
    int c  = i % C;
    int hk = i / C;
    int h  = hk / C;
    int k  = hk - h*C;
    int hc = h*C + c;
    float inv = gam[hc] / sqrtf(var[hc] + 1e-5f);
    float val = W1[i] * inv;
    g_Wf[i] = val;
    if (k == 0) g_bf[hc] = (b1[hc] - mu[hc]) * inv + bet[hc];
    if (h == 0) {
        float hi = __uint_as_float(f2tf32(val));
        float lo = val - hi;
        g_Whi[k*WPAD + c] = hi;
        g_Wlo[k*WPAD + c] = __uint_as_float(f2tf32(lo));
    }
}

// ---------------- kernel 1: dense hm head, TF32 mma.sync 3-term split ----------------
__global__ void __launch_bounds__(256, 1)
hm_kernel(const float* __restrict__ feats,
          const float* __restrict__ W2, const float* __restrict__ b2) {
    extern __shared__ float sm[];
    float* Xs  = sm + SM_XS;
    float* Wh  = sm + SM_WH;
    float* Wl  = sm + SM_WL;
    float* W2s = sm + SM_W2;
    float* bfs = sm + SM_BF;

    int tid  = threadIdx.x;
    int wid  = tid >> 5;
    int lane = tid & 31;
    int wm = wid >> 1, wn = wid & 1;       // warp tile: rows wm*32, cols wn*64

    // load weights once per block
    for (int i = tid; i < 128*WPAD/4; i += 256) {
        *reinterpret_cast<float4*>(Wh + i*4) = *reinterpret_cast<const float4*>(g_Whi + i*4);
        *reinterpret_cast<float4*>(Wl + i*4) = *reinterpret_cast<const float4*>(g_Wlo + i*4);
    }
    for (int i = tid; i < C*NCLS; i += 256) W2s[i] = W2[i];
    if (tid < C) bfs[tid] = g_bf[tid];
    float b2r[NCLS];
    #pragma unroll
    for (int j = 0; j < NCLS; j++) b2r[j] = __ldg(b2 + j);
    __syncthreads();

    for (int it = 0; it < TILES_PER_BLOCK; it++) {
        int row0 = (blockIdx.x * TILES_PER_BLOCK + it) * 128;

        // load X tile row-major
        for (int t = tid; t < 128*32; t += 256) {
            int r  = t >> 5;
            int c4 = (t & 31) << 2;
            float4 f = *reinterpret_cast<const float4*>(feats + (long)(row0 + r)*C + c4);
            *reinterpret_cast<float4*>(Xs + r*XPAD + c4) = f;
        }
        __syncthreads();

        float acc[2][8][4];
        #pragma unroll
        for (int mi = 0; mi < 2; mi++)
            #pragma unroll
            for (int ni = 0; ni < 8; ni++)
                #pragma unroll
                for (int q = 0; q < 4; q++) acc[mi][ni][q] = 0.f;

        int arow = wm*32 + (lane >> 2);
        int bcol = wn*64 + (lane >> 2);
        int klo  = lane & 3;

        #pragma unroll 4
        for (int ks = 0; ks < 16; ks++) {
            int k0 = ks * 8;
            // A fragments (hi/lo computed in-register)
            uint32_t ahi[2][4], alo[2][4];
            #pragma unroll
            for (int mi = 0; mi < 2; mi++) {
                int rb = arow + mi*16;
                #pragma unroll
                for (int j = 0; j < 4; j++) {
                    int r = rb + (j & 1)*8;
                    int k = k0 + klo + (j >> 1)*4;
                    float x = Xs[r*XPAD + k];
                    uint32_t h = f2tf32(x);
                    ahi[mi][j] = h;
                    alo[mi][j] = f2tf32(x - __uint_as_float(h));
                }
            }
            // B fragments
            uint32_t bhi[8][2], blo[8][2];
            #pragma unroll
            for (int ni = 0; ni < 8; ni++) {
                int c = bcol + ni*8;
                int ka = (k0 + klo) * WPAD + c;
                bhi[ni][0] = __float_as_uint(Wh[ka]);
                bhi[ni][1] = __float_as_uint(Wh[ka + 4*WPAD]);
                blo[ni][0] = __float_as_uint(Wl[ka]);
                blo[ni][1] = __float_as_uint(Wl[ka + 4*WPAD]);
            }
            // 3-term MMAs
            #pragma unroll
            for (int mi = 0; mi < 2; mi++)
                #pragma unroll
                for (int ni = 0; ni < 8; ni++) {
                    mma_tf32(acc[mi][ni], ahi[mi], bhi[ni]);
                    mma_tf32(acc[mi][ni], ahi[mi], blo[ni]);
                    mma_tf32(acc[mi][ni], alo[mi], bhi[ni]);
                }
        }
        __syncthreads();   // done reading Xs

        // epilogue: relu(acc + bias) -> Xs as H[row][col]
        #pragma unroll
        for (int mi = 0; mi < 2; mi++) {
            int r0 = wm*32 + mi*16 + (lane >> 2);
            #pragma unroll
            for (int ni = 0; ni < 8; ni++) {
                int c0 = wn*64 + ni*8 + 2*(lane & 3);
                Xs[r0*XPAD + c0]         = fmaxf(acc[mi][ni][0] + bfs[c0],     0.f);
                Xs[r0*XPAD + c0 + 1]     = fmaxf(acc[mi][ni][1] + bfs[c0 + 1], 0.f);
                Xs[(r0+8)*XPAD + c0]     = fmaxf(acc[mi][ni][2] + bfs[c0],     0.f);
                Xs[(r0+8)*XPAD + c0 + 1] = fmaxf(acc[mi][ni][3] + bfs[c0 + 1], 0.f);
            }
        }
        __syncthreads();

        // second linear (oc=10): 2 threads/row, 5 classes each; store RAW logits
        {
            int row = tid >> 1;
            int j0  = (tid & 1) * 5;
            float o[5];
            #pragma unroll
            for (int j = 0; j < 5; j++) o[j] = b2r[j0 + j];
            for (int kk = 0; kk < C; kk++) {
                float hv = Xs[row*XPAD + kk];
                #pragma unroll
                for (int j = 0; j < 5; j++) o[j] += hv * W2s[kk*NCLS + j0 + j];
            }
            int rrow = row0 + row;
            int b    = rrow >> 15;
            int v    = rrow & (NVOX - 1);
            #pragma unroll
            for (int j = 0; j < 5; j++)
                g_hm[((long)(b*NCLS + j0 + j))*NVOX + v] = o[j];
        }
        __syncthreads();
    }
}

// ---------------- radix helpers ----------------
__device__ __forceinline__ unsigned key_of(float f) {
    unsigned u = __float_as_uint(f);
    return (u & 0x80000000u) ? ~u : (u | 0x80000000u);
}
__device__ __forceinline__ float float_of(unsigned k) {
    unsigned u = (k & 0x80000000u) ? (k & 0x7FFFFFFFu) : ~k;
    return __uint_as_float(u);
}
__device__ __forceinline__ void hist_add(int* hist, unsigned bin, bool act) {
    unsigned lm = __activemask();
    unsigned amask = __ballot_sync(lm, act);
    if (act) {
        unsigned peers = __match_any_sync(amask, bin);
        int leader = __ffs(peers) - 1;
        if ((int)(threadIdx.x & 31) == leader)
            atomicAdd(&hist[bin], __popc(peers));
    }
}
__device__ __forceinline__ void pick_bucket(int* hist, int* ssum,
                                            unsigned* sh_prefix, unsigned* sh_mask,
                                            int* sh_rem, int shift) {
    int tid = threadIdx.x;
    if (tid < 256) ssum[tid] = hist[tid];
    __syncthreads();
    #pragma unroll
    for (int off = 1; off < 256; off <<= 1) {
        int v = 0;
        if (tid < 256 && tid + off < 256) v = ssum[tid + off];
        __syncthreads();
        if (tid < 256) ssum[tid] += v;
        __syncthreads();
    }
    int rem = *sh_rem;
    if (tid < 256) {
        int here = ssum[tid];
        int above = (tid == 255) ? 0 : ssum[tid + 1];
        if (here >= rem && above < rem) {
            *sh_rem    = rem - above;
            *sh_prefix = *sh_prefix | ((unsigned)tid << shift);
        }
    }
    __syncthreads();
    if (tid == 0) *sh_mask = *sh_mask | (0xFFu << shift);
    __syncthreads();
}

// ---------------- kernel 2: per-(b,cls,chunk) local top-500 ----------------
__global__ void __launch_bounds__(512)
topk_chunk_kernel() {
    __shared__ unsigned skey[CHUNK];
    __shared__ int hist[256];
    __shared__ int ssum[256];
    __shared__ unsigned sh_prefix, sh_mask;
    __shared__ int sh_rem, cgt, ceq;

    int blk = blockIdx.x;
    int bc  = blk >> 2, chunk = blk & 3;
    int tid = threadIdx.x, nt = blockDim.x;
    const float* src = g_hm + (long)bc * NVOX + chunk * CHUNK;

    for (int v = tid; v < CHUNK; v += nt) skey[v] = key_of(src[v]);
    if (tid == 0) { sh_prefix = 0; sh_mask = 0; sh_rem = TOPK; }
    __syncthreads();

    for (int shift = 24; shift >= 0; shift -= 8) {
        for (int i = tid; i < 256; i += nt) hist[i] = 0;
        __syncthreads();
        unsigned mask = sh_mask, pref = sh_prefix;
        for (int v = tid; v < CHUNK; v += nt) {
            unsigned k = skey[v];
            hist_add(hist, (k >> shift) & 0xFF, (k & mask) == pref);
        }
        __syncthreads();
        pick_bucket(hist, ssum, &sh_prefix, &sh_mask, &sh_rem, shift);
    }
    unsigned T = sh_prefix;
    int nEq = sh_rem;
    int nGt = TOPK - nEq;
    if (tid == 0) { cgt = 0; ceq = 0; }
    __syncthreads();

    float* outS = g_cand_score + blk * TOPK;
    int*   outV = g_cand_vox   + blk * TOPK;
    int voff = chunk * CHUNK;
    for (int v = tid; v < CHUNK; v += nt) {
        unsigned k = skey[v];
        int slot = -1;
        if (k > T)       slot = atomicAdd(&cgt, 1);
        else if (k == T) { int q = atomicAdd(&ceq, 1); if (q < nEq) slot = nGt + q; }
        if (slot >= 0) { outS[slot] = src[v]; outV[slot] = voff + v; }
    }
}

// ---------------- kernel 3: per-batch top-500 of 20000 + sort 512 ----------------
__global__ void global_topk_kernel() {
    extern __shared__ unsigned sm3[];
    unsigned* skey = sm3;
    unsigned long long* sortb = (unsigned long long*)(sm3 + CAND_PER_B);
    __shared__ int hist[256];
    __shared__ int ssum[256];
    __shared__ unsigned sh_prefix, sh_mask;
    __shared__ int sh_rem, cgt, ceq;

    int b = blockIdx.x, tid = threadIdx.x, nt = blockDim.x;
    const float* cs = g_cand_score + (long)b * CAND_PER_B;

    for (int i = tid; i < CAND_PER_B; i += nt) skey[i] = key_of(cs[i]);
    if (tid < 512) sortb[tid] = 0ull;
    if (tid == 0) { sh_prefix = 0; sh_mask = 0; sh_rem = TOPK; }
    __syncthreads();

    for (int shift = 24; shift >= 0; shift -= 8) {
        for (int i = tid; i < 256; i += nt) hist[i] = 0;
        __syncthreads();
        unsigned mask = sh_mask, pref = sh_prefix;
        for (int i = tid; i < CAND_PER_B; i += nt) {
            unsigned k = skey[i];
            hist_add(hist, (k >> shift) & 0xFF, (k & mask) == pref);
        }
        __syncthreads();
        pick_bucket(hist, ssum, &sh_prefix, &sh_mask, &sh_rem, shift);
    }
    unsigned T = sh_prefix;
    int nEq = sh_rem;
    int nGt = TOPK - nEq;
    if (tid == 0) { cgt = 0; ceq = 0; }
    __syncthreads();

    for (int i = tid; i < CAND_PER_B; i += nt) {
        unsigned k = skey[i];
        int slot = -1;
        if (k > T)       slot = atomicAdd(&cgt, 1);
        else if (k == T) { int q = atomicAdd(&ceq, 1); if (q < nEq) slot = nGt + q; }
        if (slot >= 0)
            sortb[slot] = (((unsigned long long)k) << 32) | (unsigned)i;
    }
    __syncthreads();

    for (int k = 2; k <= 512; k <<= 1) {
        for (int j = k >> 1; j > 0; j >>= 1) {
            if (tid < 512) {
                int i = tid, ixj = i ^ j;
                if (ixj > i) {
                    bool up = ((i & k) == 0);
                    unsigned long long a = sortb[i], c = sortb[ixj];
                    if (up ? (a > c) : (a < c)) { sortb[i] = c; sortb[ixj] = a; }
                }
            }
            __syncthreads();
        }
    }
    if (tid < TOPK) {
        unsigned long long it = sortb[511 - tid];
        int idx = (int)(it & 0xFFFFFFFFu);
        g_sel_score[b*TOPK + tid] = float_of((unsigned)(it >> 32));
        g_sel_cls  [b*TOPK + tid] = idx / (NCHUNK*TOPK);
        g_sel_vox  [b*TOPK + tid] = g_cand_vox[(long)b*CAND_PER_B + idx];
    }
}

// ---------------- kernel 4: 5 small heads + decode ----------------
__global__ void __launch_bounds__(128)
gather_decode_kernel(const float* __restrict__ feats, const int* __restrict__ voxel_xy,
                     const float* __restrict__ W2c, const float* __restrict__ b2c,
                     const float* __restrict__ W2z, const float* __restrict__ b2z,
                     const float* __restrict__ W2d, const float* __restrict__ b2d,
                     const float* __restrict__ W2r, const float* __restrict__ b2r,
                     const float* __restrict__ W2v, const float* __restrict__ b2v,
                     float* __restrict__ out) {
    int e0  = blockIdx.x * GD_BATCH;
    int tid = threadIdx.x;
    __shared__ float xr[GD_BATCH][C];
    __shared__ float hs[GD_BATCH][C];
    __shared__ float res[GD_BATCH][10];
    __shared__ int   svox[GD_BATCH];

    if (tid < GD_BATCH) svox[tid] = g_sel_vox[e0 + tid];
    __syncthreads();

    #pragma unroll
    for (int c = 0; c < GD_BATCH; c++) {
        int e = e0 + c;
        int row = (e / TOPK) * NVOX + svox[c];
        xr[c][tid] = feats[(long)row*C + tid];
    }
    __syncthreads();

    const float* W2p[5] = {W2c, W2z, W2d, W2r, W2v};
    const float* b2p[5] = {b2c, b2z, b2d, b2r, b2v};
    const int    ocp[5] = {2, 1, 3, 2, 2};
    const int    sbp[5] = {0, 2, 3, 6, 8};

    #pragma unroll
    for (int hh = 0; hh < 5; hh++) {
        int h = hh + 1;
        const float* w = g_Wf + h*C*C + tid;
        float acc[GD_BATCH];
        #pragma unroll
        for (int c = 0; c < GD_BATCH; c++) acc[c] = 0.f;
        #pragma unroll 4
        for (int kk = 0; kk < C; kk++) {
            float wv = w[kk*C];
            #pragma unroll
            for (int c = 0; c < GD_BATCH; c++) acc[c] += xr[c][kk] * wv;
        }
        float bb = g_bf[h*C + tid];
        #pragma unroll
        for (int c = 0; c < GD_BATCH; c++) hs[c][tid] = fmaxf(acc[c] + bb, 0.f);
        __syncthreads();

        int cand = tid >> 4, col = tid & 15;
        int oc = ocp[hh];
        if (col < oc) {
            const float* w2 = W2p[hh];
            float a2 = __ldg(b2p[hh] + col);
            for (int kk = 0; kk < C; kk++) a2 += hs[cand][kk] * __ldg(w2 + kk*oc + col);
            res[cand][sbp[hh] + col] = (hh == 2) ? expf(a2) : a2;
        }
        __syncthreads();
    }

    if (tid < GD_BATCH) {
        int e = e0 + tid;
        int b = e / TOPK, k = e % TOPK;
        float score = 1.f / (1.f + expf(-g_sel_score[e]));
        int   cls   = g_sel_cls[e];
        int   vox   = svox[tid];
        int   row   = b * NVOX + vox;
        float vx = (float)voxel_xy[row*2 + 0];
        float vy = (float)voxel_xy[row*2 + 1];
        float xs = (vx + res[tid][0]) * 0.6f - 54.0f;
        float ys = (vy + res[tid][1]) * 0.6f - 54.0f;
        float cz = res[tid][2];
        float ang = atan2f(res[tid][7], res[tid][6]);
        bool m = (xs >= -61.2f) && (xs <= 61.2f) &&
                 (ys >= -61.2f) && (ys <= 61.2f) &&
                 (cz >= -10.f)  && (cz <= 10.f)  && (score > 0.1f);
        float mf = m ? 1.f : 0.f;
        float* ob = out + (long)(b*TOPK + k) * 10;
        ob[0] = xs * mf;  ob[1] = ys * mf;  ob[2] = cz * mf;
        ob[3] = res[tid][3] * mf; ob[4] = res[tid][4] * mf; ob[5] = res[tid][5] * mf;
        ob[6] = ang * mf; ob[7] = res[tid][8] * mf; ob[8] = res[tid][9] * mf;
        ob[9] = score * mf;
        int base = b*TOPK + k;
        out[BATCH*TOPK*10                 + base] = m ? (float)(cls + 1) : 0.f;
        out[BATCH*TOPK*10 + BATCH*TOPK   + base] = (float)(vox + b*NVOX);
        out[BATCH*TOPK*10 + 2*BATCH*TOPK + base] = mf;
    }
}

// ---------------- host launcher ----------------
extern "C" void kernel_launch(void* const* d_in, const int* in_sizes, int n_in,
                              void* d_out, int out_size) {
    const float* feats    = (const float*)d_in[0];
    const int*   voxel_xy = (const int*)d_in[1];
    const float* W1  = (const float*)d_in[2];
    const float* b1  = (const float*)d_in[3];
    const float* gam = (const float*)d_in[4];
    const float* bet = (const float*)d_in[5];
    const float* mu  = (const float*)d_in[6];
    const float* var = (const float*)d_in[7];
    const float* W2_hm = (const float*)d_in[8];
    const float* b2_hm = (const float*)d_in[9];
    const float* W2_c  = (const float*)d_in[10];
    const float* b2_c  = (const float*)d_in[11];
    const float* W2_z  = (const float*)d_in[12];
    const float* b2_z  = (const float*)d_in[13];
    const float* W2_d  = (const float*)d_in[14];
    const float* b2_d  = (const float*)d_in[15];
    const float* W2_r  = (const float*)d_in[16];
    const float* b2_r  = (const float*)d_in[17];
    const float* W2_v  = (const float*)d_in[18];
    const float* b2_v  = (const float*)d_in[19];
    float* out = (float*)d_out;

    const int smem1 = SM_FLOATS * (int)sizeof(float);                 // 212480 B
    const int smem3 = CAND_PER_B * (int)sizeof(unsigned) + 512 * 8;
    cudaFuncSetAttribute(hm_kernel,          cudaFuncAttributeMaxDynamicSharedMemorySize, smem1);
    cudaFuncSetAttribute(global_topk_kernel, cudaFuncAttributeMaxDynamicSharedMemorySize, smem3);

    fold_kernel<<<(6*C*C + 255) / 256, 256>>>(W1, b1, gam, bet, mu, var);
    hm_kernel<<<HM_BLOCKS, 256, smem1>>>(feats, W2_hm, b2_hm);
    topk_chunk_kernel<<<BATCH * NCLS * NCHUNK, 512>>>();
    global_topk_kernel<<<BATCH, 1024, smem3>>>();
    gather_decode_kernel<<<BATCH * TOPK / GD_BATCH, 128>>>(feats, voxel_xy,
                                                W2_c, b2_c, W2_z, b2_z, W2_d, b2_d,
                                                W2_r, b2_r, W2_v, b2_v, out);
}

// round 7
// speedup vs baseline: 2.2786x; 1.5116x over previous
#include <cuda_runtime.h>
#include <cstdint>

#define BATCH 4
#define NVOX  32768
#define NROWS (BATCH*NVOX)
#define C     128
#define NCLS  10
#define TOPK  500
#define NCHUNK 4
#define CHUNK  (NVOX/NCHUNK)          // 8192
#define CAND_PER_B (NCLS*NCHUNK*TOPK) // 20000
#define GD_BATCH 8

// hm mma.sync config
#define HM_GRID 148
#define NTILES  (NROWS/128)           // 1024
#define XPAD 132
// dynamic smem layout in floats
#define SM_XS  0                      // [128][132] X tile / H tile
#define SM_WP  (128*XPAD)             // 16896: packed W fragments [16][16][32][4]
#define SM_W2  (SM_WP + 32768)        // 49664: [128][10]
#define SM_BF  (SM_W2 + C*NCLS)       // 50944: [128]
#define SM_FLOATS (SM_BF + 128)       // 51072 -> 204288 bytes

// ---------------- device scratch ----------------
__device__ __align__(16) float g_Wf[6*C*C];
__device__ float g_bf[6*C];
__device__ __align__(16) float g_Wpk[16*16*32*4];  // packed tf32 hi/lo fragments of W0
__device__ float g_hm[BATCH*NCLS*NVOX];            // raw logits
__device__ float g_cand_score[BATCH*CAND_PER_B];
__device__ int   g_cand_vox[BATCH*CAND_PER_B];
__device__ float g_sel_score[BATCH*TOPK];
__device__ int   g_sel_cls[BATCH*TOPK];
__device__ int   g_sel_vox[BATCH*TOPK];

__device__ __forceinline__ uint32_t f2tf32(float x) {
    uint32_t u;
    asm("cvt.rna.tf32.f32 %0, %1;" : "=r"(u) : "f"(x));
    return u;
}
__device__ __forceinline__ void mma_tf32(float* d, const uint32_t* a, const uint32_t* b) {
    asm volatile("mma.sync.aligned.m16n8k8.row.col.f32.tf32.tf32.f32 "
        "{%0,%1,%2,%3}, {%4,%5,%6,%7}, {%8,%9}, {%0,%1,%2,%3};"
        : "+f"(d[0]), "+f"(d[1]), "+f"(d[2]), "+f"(d[3])
        : "r"(a[0]), "r"(a[1]), "r"(a[2]), "r"(a[3]), "r"(b[0]), "r"(b[1]));
}

// ---------------- kernel 0: fold BN; emit packed tf32 fragments of W0 ----------------
// Fragment packing: for (ks, nt, lane): c = nt*8 + (lane>>2), klo = lane&3
//   float4 = { hi(ks*8+klo, c), hi(ks*8+klo+4, c), lo(ks*8+klo, c), lo(ks*8+klo+4, c) }
__global__ void fold_kernel(const float* __restrict__ W1, const float* __restrict__ b1,
                            const float* __restrict__ gam, const float* __restrict__ bet,
                            const float* __restrict__ mu,  const float* __restrict__ var) {
    int i = blockIdx.x * blockDim.x + threadIdx.x;
    if (i >= 6*C*C) return;
    int c  = i % C;
    int hk = i / C;
    int h  = hk / C;
    int k  = hk - h*C;
    int hc = h*C + c;
    float inv = gam[hc] / sqrtf(var[hc] + 1e-5f);
    float val = W1[i] * inv;
    g_Wf[i] = val;
    if (k == 0) g_bf[hc] = (b1[hc] - mu[hc]) * inv + bet[hc];
    if (h == 0) {
        float hi = __uint_as_float(f2tf32(val));
        float lo = __uint_as_float(f2tf32(val - hi));
        int ks   = k >> 3;
        int kk   = k & 7;
        int klo  = kk & 3;
        int half = kk >> 2;
        int lane = ((c & 7) << 2) | klo;
        int nt   = c >> 3;
        int base = (((ks*16) + nt)*32 + lane)*4;
        g_Wpk[base + half]     = hi;
        g_Wpk[base + 2 + half] = lo;
    }
}

// ---------------- kernel 1: dense hm head, TF32 mma.sync 3-term split ----------------
__global__ void __launch_bounds__(256, 1)
hm_kernel(const float* __restrict__ feats,
          const float* __restrict__ W2, const float* __restrict__ b2) {
    extern __shared__ float sm[];
    float*  Xs  = sm + SM_XS;
    float4* Wp4 = reinterpret_cast<float4*>(sm + SM_WP);
    float*  W2s = sm + SM_W2;
    float*  bfs = sm + SM_BF;

    int tid  = threadIdx.x;
    int wid  = tid >> 5;
    int lane = tid & 31;
    int wm = wid >> 1, wn = wid & 1;       // warp tile: rows wm*32, cols wn*64

    // load packed weights once per block
    for (int i = tid; i < 32768/4; i += 256)
        Wp4[i] = *reinterpret_cast<const float4*>(g_Wpk + i*4);
    for (int i = tid; i < C*NCLS; i += 256) W2s[i] = W2[i];
    if (tid < C) bfs[tid] = g_bf[tid];
    float b2r[NCLS];
    #pragma unroll
    for (int j = 0; j < NCLS; j++) b2r[j] = __ldg(b2 + j);
    __syncthreads();

    for (int tile = blockIdx.x; tile < NTILES; tile += HM_GRID) {
        int row0 = tile * 128;

        // load X tile row-major
        for (int t = tid; t < 128*32; t += 256) {
            int r  = t >> 5;
            int c4 = (t & 31) << 2;
            float4 f = *reinterpret_cast<const float4*>(feats + (long)(row0 + r)*C + c4);
            *reinterpret_cast<float4*>(Xs + r*XPAD + c4) = f;
        }
        __syncthreads();

        float acc[2][8][4];
        #pragma unroll
        for (int mi = 0; mi < 2; mi++)
            #pragma unroll
            for (int ni = 0; ni < 8; ni++)
                #pragma unroll
                for (int q = 0; q < 4; q++) acc[mi][ni][q] = 0.f;

        int arow = wm*32 + (lane >> 2);
        int klo  = lane & 3;

        #pragma unroll 4
        for (int ks = 0; ks < 16; ks++) {
            int k0 = ks * 8;
            // A fragments (hi/lo computed in-register)
            uint32_t ahi[2][4], alo[2][4];
            #pragma unroll
            for (int mi = 0; mi < 2; mi++) {
                int rb = arow + mi*16;
                #pragma unroll
                for (int j = 0; j < 4; j++) {
                    int r = rb + (j & 1)*8;
                    int k = k0 + klo + (j >> 1)*4;
                    float x = Xs[r*XPAD + k];
                    uint32_t h = f2tf32(x);
                    ahi[mi][j] = h;
                    alo[mi][j] = f2tf32(x - __uint_as_float(h));
                }
            }
            // B fragments: one float4 LDS per ni = {hi0, hi1, lo0, lo1}
            #pragma unroll
            for (int ni = 0; ni < 8; ni++) {
                int nt = wn*8 + ni;
                float4 v = Wp4[(ks*16 + nt)*32 + lane];
                uint32_t bh[2] = {__float_as_uint(v.x), __float_as_uint(v.y)};
                uint32_t bl[2] = {__float_as_uint(v.z), __float_as_uint(v.w)};
                #pragma unroll
                for (int mi = 0; mi < 2; mi++) {
                    mma_tf32(acc[mi][ni], ahi[mi], bh);
                    mma_tf32(acc[mi][ni], ahi[mi], bl);
                    mma_tf32(acc[mi][ni], alo[mi], bh);
                }
            }
        }
        __syncthreads();   // done reading Xs

        // epilogue: relu(acc + bias) -> Xs as H[row][col]
        #pragma unroll
        for (int mi = 0; mi < 2; mi++) {
            int r0 = wm*32 + mi*16 + (lane >> 2);
            #pragma unroll
            for (int ni = 0; ni < 8; ni++) {
                int c0 = wn*64 + ni*8 + 2*(lane & 3);
                Xs[r0*XPAD + c0]         = fmaxf(acc[mi][ni][0] + bfs[c0],     0.f);
                Xs[r0*XPAD + c0 + 1]     = fmaxf(acc[mi][ni][1] + bfs[c0 + 1], 0.f);
                Xs[(r0+8)*XPAD + c0]     = fmaxf(acc[mi][ni][2] + bfs[c0],     0.f);
                Xs[(r0+8)*XPAD + c0 + 1] = fmaxf(acc[mi][ni][3] + bfs[c0 + 1], 0.f);
            }
        }
        __syncthreads();

        // second linear (oc=10): 2 threads/row, 5 classes each; store RAW logits
        {
            int row = tid >> 1;
            int j0  = (tid & 1) * 5;
            float o[5];
            #pragma unroll
            for (int j = 0; j < 5; j++) o[j] = b2r[j0 + j];
            for (int kk = 0; kk < C; kk++) {
                float hv = Xs[row*XPAD + kk];
                #pragma unroll
                for (int j = 0; j < 5; j++) o[j] += hv * W2s[kk*NCLS + j0 + j];
            }
            int rrow = row0 + row;
            int b    = rrow >> 15;
            int v    = rrow & (NVOX - 1);
            #pragma unroll
            for (int j = 0; j < 5; j++)
                g_hm[((long)(b*NCLS + j0 + j))*NVOX + v] = o[j];
        }
        __syncthreads();
    }
}

// ---------------- radix helpers ----------------
__device__ __forceinline__ unsigned key_of(float f) {
    unsigned u = __float_as_uint(f);
    return (u & 0x80000000u) ? ~u : (u | 0x80000000u);
}
__device__ __forceinline__ float float_of(unsigned k) {
    unsigned u = (k & 0x80000000u) ? (k & 0x7FFFFFFFu) : ~k;
    return __uint_as_float(u);
}
__device__ __forceinline__ void hist_add(int* hist, unsigned bin, bool act) {
    unsigned lm = __activemask();
    unsigned amask = __ballot_sync(lm, act);
    if (act) {
        unsigned peers = __match_any_sync(amask, bin);
        int leader = __ffs(peers) - 1;
        if ((int)(threadIdx.x & 31) == leader)
            atomicAdd(&hist[bin], __popc(peers));
    }
}
__device__ __forceinline__ void pick_bucket(int* hist, int* ssum,
                                            unsigned* sh_prefix, unsigned* sh_mask,
                                            int* sh_rem, int shift) {
    int tid = threadIdx.x;
    if (tid < 256) ssum[tid] = hist[tid];
    __syncthreads();
    #pragma unroll
    for (int off = 1; off < 256; off <<= 1) {
        int v = 0;
        if (tid < 256 && tid + off < 256) v = ssum[tid + off];
        __syncthreads();
        if (tid < 256) ssum[tid] += v;
        __syncthreads();
    }
    int rem = *sh_rem;
    if (tid < 256) {
        int here = ssum[tid];
        int above = (tid == 255) ? 0 : ssum[tid + 1];
        if (here >= rem && above < rem) {
            *sh_rem    = rem - above;
            *sh_prefix = *sh_prefix | ((unsigned)tid << shift);
        }
    }
    __syncthreads();
    if (tid == 0) *sh_mask = *sh_mask | (0xFFu << shift);
    __syncthreads();
}

// ---------------- kernel 2: per-(b,cls,chunk) local top-500 ----------------
__global__ void __launch_bounds__(512)
topk_chunk_kernel() {
    __shared__ unsigned skey[CHUNK];
    __shared__ int hist[256];
    __shared__ int ssum[256];
    __shared__ unsigned sh_prefix, sh_mask;
    __shared__ int sh_rem, cgt, ceq;

    int blk = blockIdx.x;
    int bc  = blk >> 2, chunk = blk & 3;
    int tid = threadIdx.x, nt = blockDim.x;
    const float* src = g_hm + (long)bc * NVOX + chunk * CHUNK;

    for (int v = tid; v < CHUNK; v += nt) skey[v] = key_of(src[v]);
    if (tid == 0) { sh_prefix = 0; sh_mask = 0; sh_rem = TOPK; }
    __syncthreads();

    for (int shift = 24; shift >= 0; shift -= 8) {
        for (int i = tid; i < 256; i += nt) hist[i] = 0;
        __syncthreads();
        unsigned mask = sh_mask, pref = sh_prefix;
        for (int v = tid; v < CHUNK; v += nt) {
            unsigned k = skey[v];
            hist_add(hist, (k >> shift) & 0xFF, (k & mask) == pref);
        }
        __syncthreads();
        pick_bucket(hist, ssum, &sh_prefix, &sh_mask, &sh_rem, shift);
    }
    unsigned T = sh_prefix;
    int nEq = sh_rem;
    int nGt = TOPK - nEq;
    if (tid == 0) { cgt = 0; ceq = 0; }
    __syncthreads();

    float* outS = g_cand_score + blk * TOPK;
    int*   outV = g_cand_vox   + blk * TOPK;
    int voff = chunk * CHUNK;
    for (int v = tid; v < CHUNK; v += nt) {
        unsigned k = skey[v];
        int slot = -1;
        if (k > T)       slot = atomicAdd(&cgt, 1);
        else if (k == T) { int q = atomicAdd(&ceq, 1); if (q < nEq) slot = nGt + q; }
        if (slot >= 0) { outS[slot] = src[v]; outV[slot] = voff + v; }
    }
}

// ---------------- kernel 3: per-batch top-500 of 20000 + sort 512 ----------------
__global__ void global_topk_kernel() {
    extern __shared__ unsigned sm3[];
    unsigned* skey = sm3;
    unsigned long long* sortb = (unsigned long long*)(sm3 + CAND_PER_B);
    __shared__ int hist[256];
    __shared__ int ssum[256];
    __shared__ unsigned sh_prefix, sh_mask;
    __shared__ int sh_rem, cgt, ceq;

    int b = blockIdx.x, tid = threadIdx.x, nt = blockDim.x;
    const float* cs = g_cand_score + (long)b * CAND_PER_B;

    for (int i = tid; i < CAND_PER_B; i += nt) skey[i] = key_of(cs[i]);
    if (tid < 512) sortb[tid] = 0ull;
    if (tid == 0) { sh_prefix = 0; sh_mask = 0; sh_rem = TOPK; }
    __syncthreads();

    for (int shift = 24; shift >= 0; shift -= 8) {
        for (int i = tid; i < 256; i += nt) hist[i] = 0;
        __syncthreads();
        unsigned mask = sh_mask, pref = sh_prefix;
        for (int i = tid; i < CAND_PER_B; i += nt) {
            unsigned k = skey[i];
            hist_add(hist, (k >> shift) & 0xFF, (k & mask) == pref);
        }
        __syncthreads();
        pick_bucket(hist, ssum, &sh_prefix, &sh_mask, &sh_rem, shift);
    }
    unsigned T = sh_prefix;
    int nEq = sh_rem;
    int nGt = TOPK - nEq;
    if (tid == 0) { cgt = 0; ceq = 0; }
    __syncthreads();

    for (int i = tid; i < CAND_PER_B; i += nt) {
        unsigned k = skey[i];
        int slot = -1;
        if (k > T)       slot = atomicAdd(&cgt, 1);
        else if (k == T) { int q = atomicAdd(&ceq, 1); if (q < nEq) slot = nGt + q; }
        if (slot >= 0)
            sortb[slot] = (((unsigned long long)k) << 32) | (unsigned)i;
    }
    __syncthreads();

    for (int k = 2; k <= 512; k <<= 1) {
        for (int j = k >> 1; j > 0; j >>= 1) {
            if (tid < 512) {
                int i = tid, ixj = i ^ j;
                if (ixj > i) {
                    bool up = ((i & k) == 0);
                    unsigned long long a = sortb[i], c = sortb[ixj];
                    if (up ? (a > c) : (a < c)) { sortb[i] = c; sortb[ixj] = a; }
                }
            }
            __syncthreads();
        }
    }
    if (tid < TOPK) {
        unsigned long long it = sortb[511 - tid];
        int idx = (int)(it & 0xFFFFFFFFu);
        g_sel_score[b*TOPK + tid] = float_of((unsigned)(it >> 32));
        g_sel_cls  [b*TOPK + tid] = idx / (NCHUNK*TOPK);
        g_sel_vox  [b*TOPK + tid] = g_cand_vox[(long)b*CAND_PER_B + idx];
    }
}

// ---------------- kernel 4: 5 small heads in PARALLEL + decode ----------------
__global__ void __launch_bounds__(640)
gather_decode_kernel(const float* __restrict__ feats, const int* __restrict__ voxel_xy,
                     const float* __restrict__ W2c, const float* __restrict__ b2c,
                     const float* __restrict__ W2z, const float* __restrict__ b2z,
                     const float* __restrict__ W2d, const float* __restrict__ b2d,
                     const float* __restrict__ W2r, const float* __restrict__ b2r,
                     const float* __restrict__ W2v, const float* __restrict__ b2v,
                     float* __restrict__ out) {
    int e0  = blockIdx.x * GD_BATCH;
    int tid = threadIdx.x;
    int hh  = tid >> 7;            // head group 0..4
    int wt  = tid & 127;
    __shared__ float xr[GD_BATCH][C];
    __shared__ float hs[5][GD_BATCH][C];
    __shared__ float res[GD_BATCH][10];
    __shared__ int   svox[GD_BATCH];

    if (tid < GD_BATCH) svox[tid] = g_sel_vox[e0 + tid];
    __syncthreads();

    for (int i = tid; i < GD_BATCH*C; i += 640) {
        int c = i >> 7, k = i & 127;
        int e = e0 + c;
        int row = (e / TOPK) * NVOX + svox[c];
        xr[c][k] = feats[(long)row*C + k];
    }
    __syncthreads();

    // per-head pointers (uniform per 128-thread group)
    const float* w2; const float* bp2; int oc, sb;
    if      (hh == 0) { w2 = W2c; bp2 = b2c; oc = 2; sb = 0; }
    else if (hh == 1) { w2 = W2z; bp2 = b2z; oc = 1; sb = 2; }
    else if (hh == 2) { w2 = W2d; bp2 = b2d; oc = 3; sb = 3; }
    else if (hh == 3) { w2 = W2r; bp2 = b2r; oc = 2; sb = 6; }
    else              { w2 = W2v; bp2 = b2v; oc = 2; sb = 8; }

    {
        int h = hh + 1;
        const float* w = g_Wf + h*C*C + wt;
        float acc[GD_BATCH];
        #pragma unroll
        for (int c = 0; c < GD_BATCH; c++) acc[c] = 0.f;
        #pragma unroll 4
        for (int kk = 0; kk < C; kk++) {
            float wv = w[kk*C];
            #pragma unroll
            for (int c = 0; c < GD_BATCH; c++) acc[c] += xr[c][kk] * wv;
        }
        float bb = g_bf[h*C + wt];
        #pragma unroll
        for (int c = 0; c < GD_BATCH; c++) hs[hh][c][wt] = fmaxf(acc[c] + bb, 0.f);
    }
    __syncthreads();

    {
        int cand = wt >> 4, col = wt & 15;
        if (col < oc) {
            float a2 = __ldg(bp2 + col);
            for (int kk = 0; kk < C; kk++) a2 += hs[hh][cand][kk] * __ldg(w2 + kk*oc + col);
            res[cand][sb + col] = (hh == 2) ? expf(a2) : a2;
        }
    }
    __syncthreads();

    if (tid < GD_BATCH) {
        int e = e0 + tid;
        int b = e / TOPK, k = e % TOPK;
        float score = 1.f / (1.f + expf(-g_sel_score[e]));
        int   cls   = g_sel_cls[e];
        int   vox   = svox[tid];
        int   row   = b * NVOX + vox;
        float vx = (float)voxel_xy[row*2 + 0];
        float vy = (float)voxel_xy[row*2 + 1];
        float xs = (vx + res[tid][0]) * 0.6f - 54.0f;
        float ys = (vy + res[tid][1]) * 0.6f - 54.0f;
        float cz = res[tid][2];
        float ang = atan2f(res[tid][7], res[tid][6]);
        bool m = (xs >= -61.2f) && (xs <= 61.2f) &&
                 (ys >= -61.2f) && (ys <= 61.2f) &&
                 (cz >= -10.f)  && (cz <= 10.f)  && (score > 0.1f);
        float mf = m ? 1.f : 0.f;
        float* ob = out + (long)(b*TOPK + k) * 10;
        ob[0] = xs * mf;  ob[1] = ys * mf;  ob[2] = cz * mf;
        ob[3] = res[tid][3] * mf; ob[4] = res[tid][4] * mf; ob[5] = res[tid][5] * mf;
        ob[6] = ang * mf; ob[7] = res[tid][8] * mf; ob[8] = res[tid][9] * mf;
        ob[9] = score * mf;
        int base = b*TOPK + k;
        out[BATCH*TOPK*10                 + base] = m ? (float)(cls + 1) : 0.f;
        out[BATCH*TOPK*10 + BATCH*TOPK   + base] = (float)(vox + b*NVOX);
        out[BATCH*TOPK*10 + 2*BATCH*TOPK + base] = mf;
    }
}

// ---------------- host launcher ----------------
extern "C" void kernel_launch(void* const* d_in, const int* in_sizes, int n_in,
                              void* d_out, int out_size) {
    const float* feats    = (const float*)d_in[0];
    const int*   voxel_xy = (const int*)d_in[1];
    const float* W1  = (const float*)d_in[2];
    const float* b1  = (const float*)d_in[3];
    const float* gam = (const float*)d_in[4];
    const float* bet = (const float*)d_in[5];
    const float* mu  = (const float*)d_in[6];
    const float* var = (const float*)d_in[7];
    const float* W2_hm = (const float*)d_in[8];
    const float* b2_hm = (const float*)d_in[9];
    const float* W2_c  = (const float*)d_in[10];
    const float* b2_c  = (const float*)d_in[11];
    const float* W2_z  = (const float*)d_in[12];
    const float* b2_z  = (const float*)d_in[13];
    const float* W2_d  = (const float*)d_in[14];
    const float* b2_d  = (const float*)d_in[15];
    const float* W2_r  = (const float*)d_in[16];
    const float* b2_r  = (const float*)d_in[17];
    const float* W2_v  = (const float*)d_in[18];
    const float* b2_v  = (const float*)d_in[19];
    float* out = (float*)d_out;

    const int smem1 = SM_FLOATS * (int)sizeof(float);                 // 204288 B
    const int smem3 = CAND_PER_B * (int)sizeof(unsigned) + 512 * 8;
    cudaFuncSetAttribute(hm_kernel,          cudaFuncAttributeMaxDynamicSharedMemorySize, smem1);
    cudaFuncSetAttribute(global_topk_kernel, cudaFuncAttributeMaxDynamicSharedMemorySize, smem3);

    fold_kernel<<<(6*C*C + 255) / 256, 256>>>(W1, b1, gam, bet, mu, var);
    hm_kernel<<<HM_GRID, 256, smem1>>>(feats, W2_hm, b2_hm);
    topk_chunk_kernel<<<BATCH * NCLS * NCHUNK, 512>>>();
    global_topk_kernel<<<BATCH, 1024, smem3>>>();
    gather_decode_kernel<<<BATCH * TOPK / GD_BATCH, 640>>>(feats, voxel_xy,
                                                W2_c, b2_c, W2_z, b2_z, W2_d, b2_d,
                                                W2_r, b2_r, W2_v, b2_v, out);
}

// round 8
// speedup vs baseline: 2.3374x; 1.0258x over previous
#include <cuda_runtime.h>
#include <cstdint>

#define BATCH 4
#define NVOX  32768
#define NROWS (BATCH*NVOX)
#define C     128
#define NCLS  10
#define TOPK  500
#define NCHUNK 4
#define CHUNK  (NVOX/NCHUNK)          // 8192
#define CAND_PER_B (NCLS*NCHUNK*TOPK) // 20000
#define GD_BATCH 8

// hm mma.sync config
#define HM_GRID 148
#define NTILES  (NROWS/128)           // 1024
#define XPAD 132
// dynamic smem layout in floats
#define SM_XS  0                      // [128][132] X tile
#define SM_WP  (128*XPAD)             // 16896: packed W fragments [16][16][32][4]
#define SM_W2  (SM_WP + 32768)        // 49664: [128][10]
#define SM_BF  (SM_W2 + C*NCLS)       // 50944: [128]
#define SM_PO  (SM_BF + 128)          // 51072: [2][128][10]
#define SM_FLOATS (SM_PO + 2560)      // 53632 -> 214528 bytes

// ---------------- device scratch ----------------
__device__ __align__(16) float g_Wf[6*C*C];
__device__ float g_bf[6*C];
__device__ __align__(16) float g_Wpk[16*16*32*4];  // packed tf32 hi/lo fragments of W0
__device__ float g_hm[BATCH*NCLS*NVOX];            // raw logits
__device__ float g_cand_score[BATCH*CAND_PER_B];
__device__ int   g_cand_vox[BATCH*CAND_PER_B];
__device__ float g_sel_score[BATCH*TOPK];
__device__ int   g_sel_cls[BATCH*TOPK];
__device__ int   g_sel_vox[BATCH*TOPK];

__device__ __forceinline__ uint32_t f2tf32(float x) {
    uint32_t u;
    asm("cvt.rna.tf32.f32 %0, %1;" : "=r"(u) : "f"(x));
    return u;
}
__device__ __forceinline__ void mma_tf32(float* d, const uint32_t* a, const uint32_t* b) {
    asm volatile("mma.sync.aligned.m16n8k8.row.col.f32.tf32.tf32.f32 "
        "{%0,%1,%2,%3}, {%4,%5,%6,%7}, {%8,%9}, {%0,%1,%2,%3};"
        : "+f"(d[0]), "+f"(d[1]), "+f"(d[2]), "+f"(d[3])
        : "r"(a[0]), "r"(a[1]), "r"(a[2]), "r"(a[3]), "r"(b[0]), "r"(b[1]));
}

// ---------------- kernel 0: fold BN; emit packed tf32 fragments of W0 ----------------
__global__ void fold_kernel(const float* __restrict__ W1, const float* __restrict__ b1,
                            const float* __restrict__ gam, const float* __restrict__ bet,
                            const float* __restrict__ mu,  const float* __restrict__ var) {
    int i = blockIdx.x * blockDim.x + threadIdx.x;
    if (i >= 6*C*C) return;
    int c  = i % C;
    int hk = i / C;
    int h  = hk / C;
    int k  = hk - h*C;
    int hc = h*C + c;
    float inv = gam[hc] / sqrtf(var[hc] + 1e-5f);
    float val = W1[i] * inv;
    g_Wf[i] = val;
    if (k == 0) g_bf[hc] = (b1[hc] - mu[hc]) * inv + bet[hc];
    if (h == 0) {
        float hi = __uint_as_float(f2tf32(val));
        float lo = __uint_as_float(f2tf32(val - hi));
        int ks   = k >> 3;
        int kk   = k & 7;
        int klo  = kk & 3;
        int half = kk >> 2;
        int lane = ((c & 7) << 2) | klo;
        int nt   = c >> 3;
        int base = (((ks*16) + nt)*32 + lane)*4;
        g_Wpk[base + half]     = hi;
        g_Wpk[base + 2 + half] = lo;
    }
}

// ---------------- kernel 1: dense hm head, TF32 mma.sync 3-term split ----------------
__global__ void __launch_bounds__(256, 1)
hm_kernel(const float* __restrict__ feats,
          const float* __restrict__ W2, const float* __restrict__ b2) {
    extern __shared__ float sm[];
    float*  Xs  = sm + SM_XS;
    float4* Wp4 = reinterpret_cast<float4*>(sm + SM_WP);
    float*  W2s = sm + SM_W2;
    float*  bfs = sm + SM_BF;
    float*  po2 = sm + SM_PO;              // [2][128][10]

    int tid  = threadIdx.x;
    int wid  = tid >> 5;
    int lane = tid & 31;
    int wm = wid >> 1, wn = wid & 1;       // warp tile: rows wm*32, cols wn*64

    // load packed weights once per block
    for (int i = tid; i < 32768/4; i += 256)
        Wp4[i] = *reinterpret_cast<const float4*>(g_Wpk + i*4);
    for (int i = tid; i < C*NCLS; i += 256) W2s[i] = W2[i];
    if (tid < C) bfs[tid] = g_bf[tid];
    float b2r[NCLS];
    #pragma unroll
    for (int j = 0; j < NCLS; j++) b2r[j] = __ldg(b2 + j);
    __syncthreads();

    for (int tile = blockIdx.x; tile < NTILES; tile += HM_GRID) {
        int row0 = tile * 128;

        // load X tile row-major
        for (int t = tid; t < 128*32; t += 256) {
            int r  = t >> 5;
            int c4 = (t & 31) << 2;
            float4 f = *reinterpret_cast<const float4*>(feats + (long)(row0 + r)*C + c4);
            *reinterpret_cast<float4*>(Xs + r*XPAD + c4) = f;
        }
        __syncthreads();

        float acc[2][8][4];
        #pragma unroll
        for (int mi = 0; mi < 2; mi++)
            #pragma unroll
            for (int ni = 0; ni < 8; ni++)
                #pragma unroll
                for (int q = 0; q < 4; q++) acc[mi][ni][q] = 0.f;

        int arow = wm*32 + (lane >> 2);
        int klo  = lane & 3;

        #pragma unroll 4
        for (int ks = 0; ks < 16; ks++) {
            int k0 = ks * 8;
            uint32_t ahi[2][4], alo[2][4];
            #pragma unroll
            for (int mi = 0; mi < 2; mi++) {
                int rb = arow + mi*16;
                #pragma unroll
                for (int j = 0; j < 4; j++) {
                    int r = rb + (j & 1)*8;
                    int k = k0 + klo + (j >> 1)*4;
                    float x = Xs[r*XPAD + k];
                    uint32_t h = f2tf32(x);
                    ahi[mi][j] = h;
                    alo[mi][j] = f2tf32(x - __uint_as_float(h));
                }
            }
            #pragma unroll
            for (int ni = 0; ni < 8; ni++) {
                int nt = wn*8 + ni;
                float4 v = Wp4[(ks*16 + nt)*32 + lane];
                uint32_t bh[2] = {__float_as_uint(v.x), __float_as_uint(v.y)};
                uint32_t bl[2] = {__float_as_uint(v.z), __float_as_uint(v.w)};
                #pragma unroll
                for (int mi = 0; mi < 2; mi++) {
                    mma_tf32(acc[mi][ni], ahi[mi], bh);
                    mma_tf32(acc[mi][ni], ahi[mi], bl);
                    mma_tf32(acc[mi][ni], alo[mi], bh);
                }
            }
        }

        // ---- epilogue directly from accumulators ----
        // partial o over this thread's 16 columns, for its 4 row slots
        float po[4][NCLS];
        #pragma unroll
        for (int s = 0; s < 4; s++)
            #pragma unroll
            for (int j = 0; j < NCLS; j++) po[s][j] = 0.f;

        #pragma unroll
        for (int ni = 0; ni < 8; ni++) {
            #pragma unroll
            for (int t = 0; t < 2; t++) {
                int c = wn*64 + ni*8 + 2*(lane & 3) + t;
                float bfc = bfs[c];
                float w2l[NCLS];
                #pragma unroll
                for (int j = 0; j < NCLS; j++) w2l[j] = W2s[c*NCLS + j];
                #pragma unroll
                for (int mi = 0; mi < 2; mi++) {
                    float h0 = fmaxf(acc[mi][ni][t]     + bfc, 0.f);   // row slot mi*2+0
                    float h1 = fmaxf(acc[mi][ni][t + 2] + bfc, 0.f);   // row slot mi*2+1
                    #pragma unroll
                    for (int j = 0; j < NCLS; j++) {
                        po[mi*2 + 0][j] += h0 * w2l[j];
                        po[mi*2 + 1][j] += h1 * w2l[j];
                    }
                }
            }
        }
        // reduce over the 4 lanes of each column group
        #pragma unroll
        for (int s = 0; s < 4; s++)
            #pragma unroll
            for (int j = 0; j < NCLS; j++) {
                float v = po[s][j];
                v += __shfl_xor_sync(0xffffffff, v, 1);
                v += __shfl_xor_sync(0xffffffff, v, 2);
                po[s][j] = v;
            }
        if ((lane & 3) == 0) {
            int rbase = wm*32 + (lane >> 2);
            #pragma unroll
            for (int s = 0; s < 4; s++) {
                int row = rbase + ((s & 1) ? 8 : 0) + ((s >> 1) ? 16 : 0);
                #pragma unroll
                for (int j = 0; j < NCLS; j++)
                    po2[(wn*128 + row)*NCLS + j] = po[s][j];
            }
        }
        __syncthreads();

        // final: sum halves + bias, store RAW logits (2 threads/row, 5 classes each)
        {
            int row = tid >> 1;
            int j0  = (tid & 1) * 5;
            int rrow = row0 + row;
            int b    = rrow >> 15;
            int v    = rrow & (NVOX - 1);
            #pragma unroll
            for (int j = 0; j < 5; j++) {
                float val = po2[row*NCLS + j0 + j] + po2[(128 + row)*NCLS + j0 + j] + b2r[j0 + j];
                g_hm[((long)(b*NCLS + j0 + j))*NVOX + v] = val;
            }
        }
        __syncthreads();   // Xs + po2 free for next tile
    }
}

// ---------------- radix helpers ----------------
__device__ __forceinline__ unsigned key_of(float f) {
    unsigned u = __float_as_uint(f);
    return (u & 0x80000000u) ? ~u : (u | 0x80000000u);
}
__device__ __forceinline__ float float_of(unsigned k) {
    unsigned u = (k & 0x80000000u) ? (k & 0x7FFFFFFFu) : ~k;
    return __uint_as_float(u);
}
__device__ __forceinline__ void hist_add(int* hist, unsigned bin, bool act) {
    unsigned lm = __activemask();
    unsigned amask = __ballot_sync(lm, act);
    if (act) {
        unsigned peers = __match_any_sync(amask, bin);
        int leader = __ffs(peers) - 1;
        if ((int)(threadIdx.x & 31) == leader)
            atomicAdd(&hist[bin], __popc(peers));
    }
}
// single-warp bucket pick: 2 barriers total
__device__ __forceinline__ void pick_bucket(int* hist, unsigned* sh_prefix,
                                            int* sh_rem, int shift) {
    __syncthreads();                 // hist complete
    if (threadIdx.x < 32) {
        int lane = threadIdx.x;
        int b0 = lane * 8;
        int loc[8];
        int tot = 0;
        #pragma unroll
        for (int q = 0; q < 8; q++) { loc[q] = hist[b0 + q]; tot += loc[q]; }
        int s = tot;                 // inclusive suffix over lane totals
        #pragma unroll
        for (int off = 1; off < 32; off <<= 1) {
            int t = __shfl_down_sync(0xffffffff, s, off);
            if (lane + off < 32) s += t;
        }
        int rem = *sh_rem;
        int cum = s - tot;           // count in bins > this lane's top bin
        #pragma unroll
        for (int q = 7; q >= 0; q--) {
            int prev = cum;
            cum += loc[q];
            if (cum >= rem && prev < rem) {
                *sh_rem    = rem - prev;
                *sh_prefix = *sh_prefix | ((unsigned)(b0 + q) << shift);
            }
        }
    }
    __syncthreads();
}
__constant__ unsigned c_mask[4] = {0u, 0xFF000000u, 0xFFFF0000u, 0xFFFFFF00u};

// ---------------- kernel 2: per-(b,cls,chunk) local top-500 ----------------
__global__ void __launch_bounds__(512)
topk_chunk_kernel() {
    __shared__ unsigned skey[CHUNK];
    __shared__ int hist[256];
    __shared__ unsigned sh_prefix;
    __shared__ int sh_rem, cgt, ceq;

    int blk = blockIdx.x;
    int bc  = blk >> 2, chunk = blk & 3;
    int tid = threadIdx.x, nt = blockDim.x;
    const float* src = g_hm + (long)bc * NVOX + chunk * CHUNK;

    for (int v = tid; v < CHUNK; v += nt) skey[v] = key_of(src[v]);
    if (tid == 0) { sh_prefix = 0; sh_rem = TOPK; }
    if (tid < 256) hist[tid] = 0;
    __syncthreads();

    #pragma unroll
    for (int p = 0; p < 4; p++) {
        int shift = 24 - 8*p;
        unsigned mask = c_mask[p], pref = sh_prefix;
        for (int v = tid; v < CHUNK; v += nt) {
            unsigned k = skey[v];
            hist_add(hist, (k >> shift) & 0xFF, (k & mask) == pref);
        }
        pick_bucket(hist, &sh_prefix, &sh_rem, shift);
        if (tid < 256) hist[tid] = 0;
        if (p == 3 && tid == 0) { cgt = 0; ceq = 0; }
        __syncthreads();
    }
    unsigned T = sh_prefix;
    int nEq = sh_rem;
    int nGt = TOPK - nEq;

    float* outS = g_cand_score + blk * TOPK;
    int*   outV = g_cand_vox   + blk * TOPK;
    int voff = chunk * CHUNK;
    for (int v = tid; v < CHUNK; v += nt) {
        unsigned k = skey[v];
        int slot = -1;
        if (k > T)       slot = atomicAdd(&cgt, 1);
        else if (k == T) { int q = atomicAdd(&ceq, 1); if (q < nEq) slot = nGt + q; }
        if (slot >= 0) { outS[slot] = src[v]; outV[slot] = voff + v; }
    }
}

// ---------------- kernel 3: per-batch top-500 of 20000 (rank-by-count) ----------------
__global__ void global_topk_kernel() {
    extern __shared__ unsigned sm3[];
    unsigned* skey = sm3;                                              // [20000]
    unsigned long long* sortb = (unsigned long long*)(sm3 + CAND_PER_B); // [512]
    __shared__ int hist[256];
    __shared__ unsigned sh_prefix;
    __shared__ int sh_rem, cgt, ceq;

    int b = blockIdx.x, tid = threadIdx.x, nt = blockDim.x;
    const float* cs = g_cand_score + (long)b * CAND_PER_B;

    for (int i = tid; i < CAND_PER_B; i += nt) skey[i] = key_of(cs[i]);
    if (tid < 512) sortb[tid] = 0ull;
    if (tid == 0) { sh_prefix = 0; sh_rem = TOPK; }
    if (tid < 256) hist[tid] = 0;
    __syncthreads();

    #pragma unroll
    for (int p = 0; p < 4; p++) {
        int shift = 24 - 8*p;
        unsigned mask = c_mask[p], pref = sh_prefix;
        for (int i = tid; i < CAND_PER_B; i += nt) {
            unsigned k = skey[i];
            hist_add(hist, (k >> shift) & 0xFF, (k & mask) == pref);
        }
        pick_bucket(hist, &sh_prefix, &sh_rem, shift);
        if (tid < 256) hist[tid] = 0;
        if (p == 3 && tid == 0) { cgt = 0; ceq = 0; }
        __syncthreads();
    }
    unsigned T = sh_prefix;
    int nEq = sh_rem;
    int nGt = TOPK - nEq;

    for (int i = tid; i < CAND_PER_B; i += nt) {
        unsigned k = skey[i];
        int slot = -1;
        if (k > T)       slot = atomicAdd(&cgt, 1);
        else if (k == T) { int q = atomicAdd(&ceq, 1); if (q < nEq) slot = nGt + q; }
        if (slot >= 0)
            sortb[slot] = (((unsigned long long)k) << 32) | (unsigned)i;
    }
    __syncthreads();

    // rank-by-count over 512 entries (exactly TOPK nonzero; padding ranks >= TOPK)
    if (tid < 512) {
        unsigned long long mine = sortb[tid];
        int rank = 0;
        for (int j = 0; j < 512; j++)
            rank += (sortb[j] > mine);
        if (mine != 0ull && rank < TOPK) {
            int idx = (int)(mine & 0xFFFFFFFFu);
            g_sel_score[b*TOPK + rank] = float_of((unsigned)(mine >> 32));
            g_sel_cls  [b*TOPK + rank] = idx / (NCHUNK*TOPK);
            g_sel_vox  [b*TOPK + rank] = g_cand_vox[(long)b*CAND_PER_B + idx];
        }
    }
}

// ---------------- kernel 4: 5 small heads in PARALLEL + decode ----------------
__global__ void __launch_bounds__(640)
gather_decode_kernel(const float* __restrict__ feats, const int* __restrict__ voxel_xy,
                     const float* __restrict__ W2c, const float* __restrict__ b2c,
                     const float* __restrict__ W2z, const float* __restrict__ b2z,
                     const float* __restrict__ W2d, const float* __restrict__ b2d,
                     const float* __restrict__ W2r, const float* __restrict__ b2r,
                     const float* __restrict__ W2v, const float* __restrict__ b2v,
                     float* __restrict__ out) {
    int e0  = blockIdx.x * GD_BATCH;
    int tid = threadIdx.x;
    int hh  = tid >> 7;            // head group 0..4
    int wt  = tid & 127;
    __shared__ float xr[GD_BATCH][C];
    __shared__ float hs[5][GD_BATCH][C];
    __shared__ float res[GD_BATCH][10];
    __shared__ int   svox[GD_BATCH];

    if (tid < GD_BATCH) svox[tid] = g_sel_vox[e0 + tid];
    __syncthreads();

    for (int i = tid; i < GD_BATCH*C; i += 640) {
        int c = i >> 7, k = i & 127;
        int e = e0 + c;
        int row = (e / TOPK) * NVOX + svox[c];
        xr[c][k] = feats[(long)row*C + k];
    }
    __syncthreads();

    const float* w2; const float* bp2; int oc, sb;
    if      (hh == 0) { w2 = W2c; bp2 = b2c; oc = 2; sb = 0; }
    else if (hh == 1) { w2 = W2z; bp2 = b2z; oc = 1; sb = 2; }
    else if (hh == 2) { w2 = W2d; bp2 = b2d; oc = 3; sb = 3; }
    else if (hh == 3) { w2 = W2r; bp2 = b2r; oc = 2; sb = 6; }
    else              { w2 = W2v; bp2 = b2v; oc = 2; sb = 8; }

    {
        int h = hh + 1;
        const float* w = g_Wf + h*C*C + wt;
        float acc[GD_BATCH];
        #pragma unroll
        for (int c = 0; c < GD_BATCH; c++) acc[c] = 0.f;
        #pragma unroll 4
        for (int kk = 0; kk < C; kk++) {
            float wv = w[kk*C];
            #pragma unroll
            for (int c = 0; c < GD_BATCH; c++) acc[c] += xr[c][kk] * wv;
        }
        float bb = g_bf[h*C + wt];
        #pragma unroll
        for (int c = 0; c < GD_BATCH; c++) hs[hh][c][wt] = fmaxf(acc[c] + bb, 0.f);
    }
    __syncthreads();

    {
        int cand = wt >> 4, col = wt & 15;
        if (col < oc) {
            float a2 = __ldg(bp2 + col);
            for (int kk = 0; kk < C; kk++) a2 += hs[hh][cand][kk] * __ldg(w2 + kk*oc + col);
            res[cand][sb + col] = (hh == 2) ? expf(a2) : a2;
        }
    }
    __syncthreads();

    if (tid < GD_BATCH) {
        int e = e0 + tid;
        int b = e / TOPK, k = e % TOPK;
        float score = 1.f / (1.f + expf(-g_sel_score[e]));
        int   cls   = g_sel_cls[e];
        int   vox   = svox[tid];
        int   row   = b * NVOX + vox;
        float vx = (float)voxel_xy[row*2 + 0];
        float vy = (float)voxel_xy[row*2 + 1];
        float xs = (vx + res[tid][0]) * 0.6f - 54.0f;
        float ys = (vy + res[tid][1]) * 0.6f - 54.0f;
        float cz = res[tid][2];
        float ang = atan2f(res[tid][7], res[tid][6]);
        bool m = (xs >= -61.2f) && (xs <= 61.2f) &&
                 (ys >= -61.2f) && (ys <= 61.2f) &&
                 (cz >= -10.f)  && (cz <= 10.f)  && (score > 0.1f);
        float mf = m ? 1.f : 0.f;
        float* ob = out + (long)(b*TOPK + k) * 10;
        ob[0] = xs * mf;  ob[1] = ys * mf;  ob[2] = cz * mf;
        ob[3] = res[tid][3] * mf; ob[4] = res[tid][4] * mf; ob[5] = res[tid][5] * mf;
        ob[6] = ang * mf; ob[7] = res[tid][8] * mf; ob[8] = res[tid][9] * mf;
        ob[9] = score * mf;
        int base = b*TOPK + k;
        out[BATCH*TOPK*10                 + base] = m ? (float)(cls + 1) : 0.f;
        out[BATCH*TOPK*10 + BATCH*TOPK   + base] = (float)(vox + b*NVOX);
        out[BATCH*TOPK*10 + 2*BATCH*TOPK + base] = mf;
    }
}

// ---------------- host launcher ----------------
extern "C" void kernel_launch(void* const* d_in, const int* in_sizes, int n_in,
                              void* d_out, int out_size) {
    const float* feats    = (const float*)d_in[0];
    const int*   voxel_xy = (const int*)d_in[1];
    const float* W1  = (const float*)d_in[2];
    const float* b1  = (const float*)d_in[3];
    const float* gam = (const float*)d_in[4];
    const float* bet = (const float*)d_in[5];
    const float* mu  = (const float*)d_in[6];
    const float* var = (const float*)d_in[7];
    const float* W2_hm = (const float*)d_in[8];
    const float* b2_hm = (const float*)d_in[9];
    const float* W2_c  = (const float*)d_in[10];
    const float* b2_c  = (const float*)d_in[11];
    const float* W2_z  = (const float*)d_in[12];
    const float* b2_z  = (const float*)d_in[13];
    const float* W2_d  = (const float*)d_in[14];
    const float* b2_d  = (const float*)d_in[15];
    const float* W2_r  = (const float*)d_in[16];
    const float* b2_r  = (const float*)d_in[17];
    const float* W2_v  = (const float*)d_in[18];
    const float* b2_v  = (const float*)d_in[19];
    float* out = (float*)d_out;

    const int smem1 = SM_FLOATS * (int)sizeof(float);                 // 214528 B
    const int smem3 = CAND_PER_B * (int)sizeof(unsigned) + 512 * 8;
    cudaFuncSetAttribute(hm_kernel,          cudaFuncAttributeMaxDynamicSharedMemorySize, smem1);
    cudaFuncSetAttribute(global_topk_kernel, cudaFuncAttributeMaxDynamicSharedMemorySize, smem3);

    fold_kernel<<<(6*C*C + 255) / 256, 256>>>(W1, b1, gam, bet, mu, var);
    hm_kernel<<<HM_GRID, 256, smem1>>>(feats, W2_hm, b2_hm);
    topk_chunk_kernel<<<BATCH * NCLS * NCHUNK, 512>>>();
    global_topk_kernel<<<BATCH, 1024, smem3>>>();
    gather_decode_kernel<<<BATCH * TOPK / GD_BATCH, 640>>>(feats, voxel_xy,
                                                W2_c, b2_c, W2_z, b2_z, W2_d, b2_d,
                                                W2_r, b2_r, W2_v, b2_v, out);
}